// round 15
// baseline (speedup 1.0000x reference)
#include <cuda_runtime.h>
#include <cuda_bf16.h>
#include <math.h>

// Problem constants
#define QLEN 512
#define MLEN 512
#define KLEN 1024
#define RLEN 1536
#define BATCH 4
#define DM 1024
#define NH 16
#define DH 64
#define SCALE 0.125f
#define LN_EPS 1e-3f

// Scratch (device globals).  "_u" arrays hold packed bf16 pairs.
__device__ unsigned g_ab_u [10240 * 512];  // [mems(2048); h(2048); r(6144)]
__device__ unsigned g_wpk_u[4 * 1024 * 512]; // proj weights [w][n][k2] (k-contig)
__device__ unsigned g_wob_u[1024 * 512];   // wo bf16 [h][1024]
__device__ unsigned g_qb_u [2048 * 512];   // q_head bf16
__device__ unsigned g_kb_u [4096 * 512];   // k_head bf16 (pre-scaled by SCALE)
__device__ unsigned g_vb_u [4096 * 512];   // v_head bf16
__device__ unsigned g_krb_u[6144 * 512];   // k_r bf16 (pre-scaled by SCALE)
__device__ unsigned g_avb_u[2048 * 512];   // attn_vec bf16
__device__ float g_e [512 * 4 * 16];       // de = SCALE*(e1-e0) [i][b][n]
__device__ float g_u [4096 * 16];          // rwb·k_scaled
__device__ float g_t [6144 * 16];          // rrb·kr_scaled
__device__ unsigned char g_code[4 * 512 * 1024]; // [b][i][j]
__device__ float g_ao[2048 * 1024];        // attn_out (pre-LN, fp32)

// ---------------------------------------------------------------------------
// helpers
// ---------------------------------------------------------------------------
__device__ __forceinline__ unsigned pk2(float lo, float hi) {
    unsigned r;
    asm("cvt.rn.bf16x2.f32 %0, %1, %2;" : "=r"(r) : "f"(hi), "f"(lo));
    return r;
}
__device__ __forceinline__ float bf_lo(unsigned u) { return __uint_as_float(u << 16); }
__device__ __forceinline__ float bf_hi(unsigned u) { return __uint_as_float(u & 0xffff0000u); }

__device__ __forceinline__ void mma_bf16(float* d, const unsigned* a,
                                         unsigned b0, unsigned b1) {
    asm volatile(
        "mma.sync.aligned.m16n8k16.row.col.f32.bf16.bf16.f32 "
        "{%0,%1,%2,%3}, {%4,%5,%6,%7}, {%8,%9}, {%0,%1,%2,%3};\n"
        : "+f"(d[0]), "+f"(d[1]), "+f"(d[2]), "+f"(d[3])
        : "r"(a[0]), "r"(a[1]), "r"(a[2]), "r"(a[3]), "r"(b0), "r"(b1));
}

__device__ __forceinline__ void cpa16(void* dst, const void* src) {
    unsigned d = (unsigned)__cvta_generic_to_shared(dst);
    asm volatile("cp.async.cg.shared.global [%0], [%1], 16;\n" :: "r"(d), "l"(src));
}
#define CP_COMMIT() asm volatile("cp.async.commit_group;\n")
#define CP_WAIT0()  asm volatile("cp.async.wait_group 0;\n")
#define CP_WAIT1()  asm volatile("cp.async.wait_group 1;\n")
#define CP_WAIT2()  asm volatile("cp.async.wait_group 2;\n")

__device__ __forceinline__ void ldsm_x4(unsigned& r0, unsigned& r1,
                                        unsigned& r2, unsigned& r3, const void* p) {
    unsigned a = (unsigned)__cvta_generic_to_shared(p);
    asm volatile("ldmatrix.sync.aligned.m8n8.x4.shared.b16 {%0,%1,%2,%3}, [%4];"
                 : "=r"(r0), "=r"(r1), "=r"(r2), "=r"(r3) : "r"(a));
}
__device__ __forceinline__ void ldsm_x4_t(unsigned& r0, unsigned& r1,
                                          unsigned& r2, unsigned& r3, const void* p) {
    unsigned a = (unsigned)__cvta_generic_to_shared(p);
    asm volatile("ldmatrix.sync.aligned.m8n8.x4.trans.shared.b16 {%0,%1,%2,%3}, [%4];"
                 : "=r"(r0), "=r"(r1), "=r"(r2), "=r"(r3) : "r"(a));
}

// 4-panel ring slab index for kr/tb (panel = absolute row / 64)
#define SLAB4(m) (((((m) >> 6) & 3) << 6) + ((m) & 63))

// ---------------------------------------------------------------------------
// prep: fp32->bf16 casts + code bytes + weight pack (fused).
// bid [0,11264): cast ; [11264,19456): code ; [19456,21504): pack
// ---------------------------------------------------------------------------
__global__ __launch_bounds__(256) void prep_kernel(
    const float* __restrict__ mems, const float* __restrict__ h,
    const float* __restrict__ r, const float* __restrict__ wo,
    const float* __restrict__ seg_mat, const float* __restrict__ attn_mask,
    const float* __restrict__ wq, const float* __restrict__ wk,
    const float* __restrict__ wv, const float* __restrict__ wr)
{
    __shared__ unsigned tile[32][33];
    int bid = blockIdx.x;
    if (bid < 11264) {
        int idx = bid * 256 + threadIdx.x;
        int row = idx >> 8, p4 = idx & 255;
        const float* src;
        unsigned* dst;
        if (row < 2048)      { src = mems + (size_t)row * 1024;          dst = g_ab_u + (size_t)row * 512; }
        else if (row < 4096) { src = h + (size_t)(row - 2048) * 1024;    dst = g_ab_u + (size_t)row * 512; }
        else if (row < 10240){ src = r + (size_t)(row - 4096) * 1024;    dst = g_ab_u + (size_t)row * 512; }
        else                 { src = wo + (size_t)(row - 10240) * 1024;  dst = g_wob_u + (size_t)(row - 10240) * 512; }
        float4 v = *(const float4*)(src + p4 * 4);
        uint2 o;
        o.x = pk2(v.x, v.y);
        o.y = pk2(v.z, v.w);
        *(uint2*)(dst + p4 * 2) = o;
    } else if (bid < 19456) {
        int idx = (bid - 11264) * 256 + threadIdx.x;
        int b = idx & 3;
        int ij = idx >> 2;
        unsigned char c = (seg_mat[(size_t)idx * 2 + 1] != 0.f) ? 1 : 0;
        if (attn_mask[idx] != 0.f) c |= 2;
        g_code[((size_t)b << 19) + ij] = c;
    } else {
        // weight pack: fp32 [k][n] -> bf16 pairs [w][n][k2]
        int pb = bid - 19456;                // < 2048
        int w = pb >> 9;
        int rem = pb & 511;
        int k2base = (rem & 15) * 32;
        int nnbase = (rem >> 4) * 32;
        const float* W = (w == 0) ? wq : (w == 1) ? wk : (w == 2) ? wv : wr;
        const int tx = threadIdx.x & 31, ty = threadIdx.x >> 5;
#pragma unroll
        for (int i = 0; i < 4; i++) {
            int k2 = k2base + ty + 8 * i;
            tile[ty + 8 * i][tx] = pk2(W[(size_t)(2 * k2) * 1024 + nnbase + tx],
                                       W[(size_t)(2 * k2 + 1) * 1024 + nnbase + tx]);
        }
        __syncthreads();
#pragma unroll
        for (int i = 0; i < 4; i++) {
            int nn = nnbase + ty + 8 * i;
            g_wpk_u[(size_t)w * 524288 + (size_t)nn * 512 + k2base + tx] = tile[tx][ty + 8 * i];
        }
    }
}

// ---------------------------------------------------------------------------
// Projection GEMM (bf16, cp.async 4-stage, ldmatrix frags).
// ---------------------------------------------------------------------------
#define PSTG 4
#define PJA 3072
#define PROJ_SMEM ((PSTG * 2 * PJA) * 4)   // 98,304 B

__global__ __launch_bounds__(256, 2) void proj_mma()
{
    extern __shared__ unsigned psm[];
    unsigned* Asm = psm;
    unsigned* Bsm = psm + PSTG * PJA;

    const int rowbase = blockIdx.y * 128;
    const int colbase = blockIdx.x * 128;

    int abase, wsel, segbase;
    unsigned* Cu;
    float csc;
    if (rowbase < 2048)        { wsel = 0; segbase = 0;     abase = 2048; Cu = g_qb_u;  csc = 1.f;   }
    else if (rowbase < 6144)   { wsel = 1; segbase = 2048;  abase = 0;    Cu = g_kb_u;  csc = SCALE; }
    else if (rowbase < 10240)  { wsel = 2; segbase = 6144;  abase = 0;    Cu = g_vb_u;  csc = 1.f;   }
    else                       { wsel = 3; segbase = 10240; abase = 4096; Cu = g_krb_u; csc = SCALE; }
    const int crb = rowbase - segbase;

    const int tid = threadIdx.x;
    const int lane = tid & 31, warp = tid >> 5;
    const int wm = warp & 3, wn = warp >> 2;
    const int grp = lane >> 2, thr = lane & 3;
    const int rowA = (lane & 7) + (lane & 8);
    const int koA  = (lane & 16) >> 2;
    const int rowB = (lane & 7) + ((lane & 16) >> 1);
    const int kB   = (lane & 8) >> 1;

    const int arw = tid >> 1;
    const int asub = tid & 1;
    const unsigned* asrc = g_ab_u + (size_t)(abase + crb + arw) * 512 + asub * 8;
    const unsigned* bsrc = g_wpk_u + (size_t)wsel * 524288 + (size_t)(colbase + arw) * 512 + asub * 8;

    float acc[2][8][4];
#pragma unroll
    for (int mf = 0; mf < 2; mf++)
#pragma unroll
        for (int nf = 0; nf < 8; nf++)
#pragma unroll
            for (int q = 0; q < 4; q++) acc[mf][nf][q] = 0.f;

#define PROJ_ISSUE(it)                                                          \
    {                                                                           \
        int s_ = (it) & 3;                                                      \
        int k2base_ = (it) * 16;                                                \
        unsigned* ad = Asm + s_ * PJA + asub * 1536 + arw * 12;                 \
        cpa16(ad,     asrc + k2base_);                                          \
        cpa16(ad + 4, asrc + k2base_ + 4);                                      \
        unsigned* bd = Bsm + s_ * PJA + asub * 1536 + arw * 12;                 \
        cpa16(bd,     bsrc + k2base_);                                          \
        cpa16(bd + 4, bsrc + k2base_ + 4);                                      \
        CP_COMMIT();                                                            \
    }

    PROJ_ISSUE(0);
    PROJ_ISSUE(1);
    PROJ_ISSUE(2);

    for (int it = 0; it < 32; it++) {
        if (it >= 30) { CP_WAIT0(); } else { CP_WAIT2(); }
        __syncthreads();
        if (it + 3 < 32) PROJ_ISSUE(it + 3);
        const unsigned* Ast = Asm + (it & 3) * PJA;
        const unsigned* Bst = Bsm + (it & 3) * PJA;
#pragma unroll
        for (int s = 0; s < 2; s++) {
            const unsigned* As_ = Ast + s * 1536;
            const unsigned* Bs_ = Bst + s * 1536;
            unsigned a[2][4], bb[8][2];
#pragma unroll
            for (int mf = 0; mf < 2; mf++)
                ldsm_x4(a[mf][0], a[mf][1], a[mf][2], a[mf][3],
                        As_ + (wm * 32 + mf * 16 + rowA) * 12 + koA);
#pragma unroll
            for (int nf0 = 0; nf0 < 8; nf0 += 2) {
                unsigned t0, t1, t2, t3;
                ldsm_x4(t0, t1, t2, t3, Bs_ + (wn * 64 + nf0 * 8 + rowB) * 12 + kB);
                bb[nf0][0] = t0; bb[nf0][1] = t1;
                bb[nf0 + 1][0] = t2; bb[nf0 + 1][1] = t3;
            }
#pragma unroll
            for (int mf = 0; mf < 2; mf++)
#pragma unroll
                for (int nf = 0; nf < 8; nf++)
                    mma_bf16(acc[mf][nf], a[mf], bb[nf][0], bb[nf][1]);
        }
    }
#pragma unroll
    for (int mf = 0; mf < 2; mf++)
#pragma unroll
        for (int nf = 0; nf < 8; nf++) {
            int rr = crb + wm * 32 + mf * 16 + grp;
            int c2 = (colbase >> 1) + wn * 32 + nf * 4 + thr;
            Cu[(size_t)rr * 512 + c2] = pk2(acc[mf][nf][0] * csc, acc[mf][nf][1] * csc);
            Cu[(size_t)(rr + 8) * 512 + c2] = pk2(acc[mf][nf][2] * csc, acc[mf][nf][3] * csc);
        }
#undef PROJ_ISSUE
}

// ---------------------------------------------------------------------------
// Output GEMM (bf16, 4-stage, ldmatrix frags): g_ao = g_avb @ wob^T.
// 64x128 tiles, grid (8,32)=256 blocks. 8 warps = 2m x 4n, warp tile 32x32.
// ---------------------------------------------------------------------------
#define OJS 4608
#define OUT_SMEM ((PSTG * OJS) * 4)    // 73,728 B

__global__ __launch_bounds__(256, 2) void out_mma()
{
    extern __shared__ unsigned psm[];

    const int rowbase = blockIdx.y * 64;
    const int colbase = blockIdx.x * 128;
    const int tid = threadIdx.x;
    const int lane = tid & 31, warp = tid >> 5;
    const int wm = warp & 1, wn = warp >> 1;
    const int grp = lane >> 2, thr = lane & 3;
    const int rowA = (lane & 7) + (lane & 8);
    const int koA  = (lane & 16) >> 2;
    const int rowB = (lane & 7) + ((lane & 16) >> 1);
    const int kB   = (lane & 8) >> 1;

    float acc[2][4][4];
#pragma unroll
    for (int mf = 0; mf < 2; mf++)
#pragma unroll
        for (int nf = 0; nf < 4; nf++)
#pragma unroll
            for (int q = 0; q < 4; q++) acc[mf][nf][q] = 0.f;

#define OUT_ISSUE(it)                                                           \
    {                                                                           \
        int s_ = (it) & 3;                                                      \
        int k2base_ = (it) * 16;                                                \
        {                                                                       \
            int row_ = tid >> 2;                                                \
            int sub_ = (tid & 2) >> 1;                                          \
            int half_ = tid & 1;                                                \
            cpa16(psm + s_ * OJS + sub_ * 768 + row_ * 12 + half_ * 4,          \
                  g_avb_u + (size_t)(rowbase + row_) * 512 + k2base_ +          \
                  sub_ * 8 + half_ * 4);                                        \
        }                                                                       \
        for (int t_ = tid; t_ < 512; t_ += 256) {                               \
            int row_ = t_ >> 2;                                                 \
            int sub_ = (t_ & 2) >> 1;                                           \
            int half_ = t_ & 1;                                                 \
            cpa16(psm + s_ * OJS + 1536 + sub_ * 1536 + row_ * 12 + half_ * 4,  \
                  g_wob_u + (size_t)(colbase + row_) * 512 + k2base_ +          \
                  sub_ * 8 + half_ * 4);                                        \
        }                                                                       \
        CP_COMMIT();                                                            \
    }

    OUT_ISSUE(0);
    OUT_ISSUE(1);
    OUT_ISSUE(2);

    for (int it = 0; it < 32; it++) {
        if (it >= 30) { CP_WAIT0(); } else { CP_WAIT2(); }
        __syncthreads();
        if (it + 3 < 32) OUT_ISSUE(it + 3);
        const unsigned* stg = psm + (it & 3) * OJS;
#pragma unroll
        for (int s = 0; s < 2; s++) {
            const unsigned* As_ = stg + s * 768;
            const unsigned* Bs_ = stg + 1536 + s * 1536;
            unsigned a[2][4], bb[4][2];
#pragma unroll
            for (int mf = 0; mf < 2; mf++)
                ldsm_x4(a[mf][0], a[mf][1], a[mf][2], a[mf][3],
                        As_ + (wm * 32 + mf * 16 + rowA) * 12 + koA);
#pragma unroll
            for (int nf0 = 0; nf0 < 4; nf0 += 2) {
                unsigned t0, t1, t2, t3;
                ldsm_x4(t0, t1, t2, t3, Bs_ + (wn * 32 + nf0 * 8 + rowB) * 12 + kB);
                bb[nf0][0] = t0; bb[nf0][1] = t1;
                bb[nf0 + 1][0] = t2; bb[nf0 + 1][1] = t3;
            }
#pragma unroll
            for (int mf = 0; mf < 2; mf++)
#pragma unroll
                for (int nf = 0; nf < 4; nf++)
                    mma_bf16(acc[mf][nf], a[mf], bb[nf][0], bb[nf][1]);
        }
    }
#pragma unroll
    for (int mf = 0; mf < 2; mf++)
#pragma unroll
        for (int nf = 0; nf < 4; nf++) {
            int rr = rowbase + wm * 32 + mf * 16 + grp;
            int cc = colbase + wn * 32 + nf * 8 + thr * 2;
            *(float2*)&g_ao[(size_t)rr * 1024 + cc] = make_float2(acc[mf][nf][0], acc[mf][nf][1]);
            *(float2*)&g_ao[(size_t)(rr + 8) * 1024 + cc] = make_float2(acc[mf][nf][2], acc[mf][nf][3]);
        }
#undef OUT_ISSUE
}

// ---------------------------------------------------------------------------
// post: 8 rows per block, warp n handles head n, fully coalesced.
// ---------------------------------------------------------------------------
__global__ __launch_bounds__(512) void post_kernel(
    const float* __restrict__ rsb, const float* __restrict__ seg_embed,
    const float* __restrict__ rwb, const float* __restrict__ rrb)
{
    const int n = threadIdx.x >> 5, lane = threadIdx.x & 31;
    if (blockIdx.x < 256) {
        const int rbase = blockIdx.x * 8;       // rows (i*4+b)
        float2 rb = *(const float2*)(rsb + n * 64 + 2 * lane);
        float2 s0 = *(const float2*)(seg_embed + n * 64 + 2 * lane);
        float2 s1 = *(const float2*)(seg_embed + 1024 + n * 64 + 2 * lane);
        unsigned uu[8];
#pragma unroll
        for (int rr = 0; rr < 8; rr++)
            uu[rr] = g_qb_u[(size_t)(rbase + rr) * 512 + n * 32 + lane];
#pragma unroll
        for (int rr = 0; rr < 8; rr++) {
            float q1 = bf_lo(uu[rr]) + rb.x;
            float q2 = bf_hi(uu[rr]) + rb.y;
            float p0 = q1 * s0.x + q2 * s0.y;
            float p1 = q1 * s1.x + q2 * s1.y;
#pragma unroll
            for (int o = 16; o; o >>= 1) {
                p0 += __shfl_xor_sync(0xffffffffu, p0, o);
                p1 += __shfl_xor_sync(0xffffffffu, p1, o);
            }
            if (lane == 0) g_e[(size_t)(rbase + rr) * 16 + n] = (p1 - p0) * SCALE;
        }
    } else {
        int rbase = (blockIdx.x - 256) * 8;
        const unsigned* src;
        const float* bias;
        float* dst;
        if (rbase < 4096) {
            src = g_kb_u + (size_t)rbase * 512;
            bias = rwb; dst = g_u + (size_t)rbase * 16;
        } else {
            src = g_krb_u + (size_t)(rbase - 4096) * 512;
            bias = rrb; dst = g_t + (size_t)(rbase - 4096) * 16;
        }
        float2 rb = *(const float2*)(bias + n * 64 + 2 * lane);
        unsigned uu[8];
#pragma unroll
        for (int rr = 0; rr < 8; rr++)
            uu[rr] = src[(size_t)rr * 512 + n * 32 + lane];
#pragma unroll
        for (int rr = 0; rr < 8; rr++) {
            float p = bf_lo(uu[rr]) * rb.x + bf_hi(uu[rr]) * rb.y;
#pragma unroll
            for (int o = 16; o; o >>= 1) p += __shfl_xor_sync(0xffffffffu, p, o);
            if (lane == 0) dst[(size_t)rr * 16 + n] = p;
        }
    }
}

// ---------------------------------------------------------------------------
// Fused attention (R13 design): warp-local, ldmatrix frags, software-pipelined
// j-loop, 4-panel kr ring, P aliased onto Gw. ub loads as float2 (32 threads).
// smem 110,848 B -> 2 blocks/SM.
// ---------------------------------------------------------------------------
#define ATT_SMEM_BYTES (27712 * 4)

__global__ __launch_bounds__(256, 2) void attn_kernel()
{
    extern __shared__ unsigned smu[];
    unsigned* ksu2 = smu;                       // 2 x [64 x 36]
    unsigned* kru  = smu + 4608;                // 256 x 36 (4-panel ring)
    unsigned* vsu  = smu + 13824;               // 64 x 36
    float* Gw  = (float*)(smu + 16128);         // 8 x [16 x 88]  (P aliases)
    float* ub  = (float*)(smu + 27392);         // 64
    float* tb2 = (float*)(smu + 27456);         // 256 (4-panel ring)
    const __nv_bfloat16* vsb = (const __nv_bfloat16*)vsu;  // row stride 72 bf16

    const int b = blockIdx.x >> 4, n = blockIdx.x & 15;
    const int i0 = blockIdx.y * 128;
    const int tid = threadIdx.x;
    const int wm = tid >> 5, lane = tid & 31;
    const int grp = lane >> 2, thr = lane & 3;
    const int r0 = wm * 16 + grp;               // local rows r0, r0+8

    float* Gwp = Gw + wm * (16 * 88);
    unsigned* Pwp = (unsigned*)Gwp;             // alias (rows stride 36 u32)

    const int row16 = (lane & 7) + ((lane & 16) >> 1);  // B-frag rows
    const int koB   = (lane & 8) >> 1;
    const int rowA  = (lane & 7) + (lane & 8);          // A-frag rows
    const int koA   = (lane & 16) >> 2;
    const int rowV  = lane & 15;
    const int colV8 = (lane & 16) >> 1;

    // ---- q fragments straight from global bf16 ----
    unsigned qa[4][4];
#pragma unroll
    for (int kc = 0; kc < 4; kc++) {
        size_t b0 = ((size_t)(i0 + r0) * 4 + b) * 512 + n * 32 + kc * 8;
        size_t b1 = ((size_t)(i0 + r0 + 8) * 4 + b) * 512 + n * 32 + kc * 8;
        qa[kc][0] = g_qb_u[b0 + thr];
        qa[kc][1] = g_qb_u[b1 + thr];
        qa[kc][2] = g_qb_u[b0 + thr + 4];
        qa[kc][3] = g_qb_u[b1 + thr + 4];
    }

    float de0 = g_e[((size_t)(i0 + r0) * 4 + b) * 16 + n];
    float de1 = g_e[((size_t)(i0 + r0 + 8) * 4 + b) * 16 + n];

    float oacc[8][4];
#pragma unroll
    for (int nt = 0; nt < 8; nt++)
#pragma unroll
        for (int q = 0; q < 4; q++) oacc[nt][q] = 0.f;
    float rmax[2] = {-3.0e38f, -3.0e38f};
    float rsum[2] = {0.f, 0.f};

    const unsigned char* codeRow0 = g_code + ((size_t)b << 19) + (size_t)(i0 + r0) * 1024;
    const unsigned char* codeRow1 = codeRow0 + 8 * 1024;

    // ---- prologue: K0 + kr window0 (3 panels) ----
    const int base0 = 384 - i0;
    for (int t = tid; t < 512; t += 256) {
        int row = t >> 3, c = (t & 7) * 4;
        cpa16(&ksu2[row * 36 + c],
              g_kb_u + ((size_t)row * 4 + b) * 512 + n * 32 + c);
    }
    for (int t = tid; t < 192 * 8; t += 256) {
        int o = t >> 3, c = (t & 7) * 4;
        cpa16(&kru[SLAB4(base0 + o) * 36 + c],
              g_krb_u + ((size_t)(base0 + o) * 4 + b) * 512 + n * 32 + c);
    }
    CP_COMMIT();
    if (tid < 192)
        tb2[SLAB4(base0 + tid)] = g_t[((size_t)(base0 + tid) * 4 + b) * 16 + n];

    for (int j0 = 0; j0 < KLEN; j0 += 64) {
        const int ji = j0 >> 6;
        const int base = j0 - i0 + 384;
        __syncthreads();                         // prior-iter reads done
        // ---- issue V(j) ----
        for (int t = tid; t < 512; t += 256) {
            int row = t >> 3, c = (t & 7) * 4;
            cpa16(&vsu[row * 36 + c],
                  g_vb_u + ((size_t)(j0 + row) * 4 + b) * 512 + n * 32 + c);
        }
        CP_COMMIT();
        // ---- issue K(j+1) + kr-panel(j+1) (prefetch one iter ahead) ----
        if (j0 + 64 < KLEN) {
            unsigned* ksn = ksu2 + ((ji + 1) & 1) * 2304;
            for (int t = tid; t < 512; t += 256) {
                int row = t >> 3, c = (t & 7) * 4;
                cpa16(&ksn[row * 36 + c],
                      g_kb_u + ((size_t)(j0 + 64 + row) * 4 + b) * 512 + n * 32 + c);
            }
            for (int t = tid; t < 512; t += 256) {
                int o = 192 + (t >> 3), c = (t & 7) * 4;
                cpa16(&kru[SLAB4(base + o) * 36 + c],
                      g_krb_u + ((size_t)(base + o) * 4 + b) * 512 + n * 32 + c);
            }
        }
        CP_COMMIT();
        // ---- scalar ub(j) (float2, 32 threads) + tb panel(j+1) ----
        if (tid < 32) {
            float2 uv;
            uv.x = g_u[((size_t)(j0 + 2 * tid) * 4 + b) * 16 + n];
            uv.y = g_u[((size_t)(j0 + 2 * tid + 1) * 4 + b) * 16 + n];
            *(float2*)&ub[2 * tid] = uv;
        } else if (tid >= 64 && tid < 128 && j0 + 64 < KLEN) {
            int o = 192 + (tid - 64);
            tb2[SLAB4(base + o)] = g_t[((size_t)(base + o) * 4 + b) * 16 + n];
        }
        CP_WAIT2();          // completes group with K(j)/kr(j) (issued iter j-1)
        __syncthreads();

        // ---- S = q @ k^T ----
        const unsigned* ksc = ksu2 + (ji & 1) * 2304;
        float sacc[8][4];
#pragma unroll
        for (int nt = 0; nt < 8; nt++)
#pragma unroll
            for (int q = 0; q < 4; q++) sacc[nt][q] = 0.f;
#pragma unroll
        for (int kc = 0; kc < 4; kc++) {
#pragma unroll
            for (int p = 0; p < 4; p++) {
                unsigned k0, k1, k2, k3;
                ldsm_x4(k0, k1, k2, k3, &ksc[(16 * p + row16) * 36 + kc * 8 + koB]);
                mma_bf16(sacc[2 * p], qa[kc], k0, k1);
                mma_bf16(sacc[2 * p + 1], qa[kc], k2, k3);
            }
        }

        // ---- per-warp band G (16 x 80), +t folded at store (float2) ----
        const int woff = 112 - wm * 16;
#pragma unroll
        for (int p = 0; p < 5; p++) {
            int o = woff + 16 * p + row16;
            int srow = SLAB4(base + o);
            float ga[4] = {0.f, 0.f, 0.f, 0.f};
            float gb[4] = {0.f, 0.f, 0.f, 0.f};
#pragma unroll
            for (int kc = 0; kc < 4; kc++) {
                unsigned k0, k1, k2, k3;
                ldsm_x4(k0, k1, k2, k3, &kru[srow * 36 + kc * 8 + koB]);
                mma_bf16(ga, qa[kc], k0, k1);
                mma_bf16(gb, qa[kc], k2, k3);
            }
            int g0 = 16 * p + 2 * thr;
            int oA = woff + g0;
            float2 tA = *(float2*)&tb2[SLAB4(base + oA)];
            int oB = oA + 8;
            float2 tB = *(float2*)&tb2[SLAB4(base + oB)];
            *(float2*)&Gwp[grp * 88 + g0]           = make_float2(ga[0] + tA.x, ga[1] + tA.y);
            *(float2*)&Gwp[(grp + 8) * 88 + g0]     = make_float2(ga[2] + tA.x, ga[3] + tA.y);
            *(float2*)&Gwp[grp * 88 + g0 + 8]       = make_float2(gb[0] + tB.x, gb[1] + tB.y);
            *(float2*)&Gwp[(grp + 8) * 88 + g0 + 8] = make_float2(gb[2] + tB.x, gb[3] + tB.y);
        }
        __syncwarp();

        // ---- assemble logits, warp-local row maxes ----
        float mx0 = -3.0e38f, mx1 = -3.0e38f;
#pragma unroll
        for (int nt = 0; nt < 8; nt++) {
            int c = nt * 8 + 2 * thr;
            int gi  = c - grp + 16;
            int gi2 = c - grp + 8;
            float G00, G01, G10, G11;
            if ((grp & 1) == 0) {
                float2 fa = *(float2*)&Gwp[grp * 88 + gi];
                float2 fb = *(float2*)&Gwp[(grp + 8) * 88 + gi2];
                G00 = fa.x; G01 = fa.y; G10 = fb.x; G11 = fb.y;
            } else {
                G00 = Gwp[grp * 88 + gi];
                G01 = Gwp[grp * 88 + gi + 1];
                G10 = Gwp[(grp + 8) * 88 + gi2];
                G11 = Gwp[(grp + 8) * 88 + gi2 + 1];
            }
            unsigned short w0 = *(const unsigned short*)(codeRow0 + j0 + c);
            unsigned short w1 = *(const unsigned short*)(codeRow1 + j0 + c);
            float2 uu = *(float2*)&ub[c];
            float v;
            v = sacc[nt][0] + G00 + uu.x + ((w0 & 1) ? de0 : 0.f);
            if (w0 & 2) v -= 1e30f;
            sacc[nt][0] = v; mx0 = fmaxf(mx0, v);
            v = sacc[nt][1] + G01 + uu.y + ((w0 & 256) ? de0 : 0.f);
            if (w0 & 512) v -= 1e30f;
            sacc[nt][1] = v; mx0 = fmaxf(mx0, v);
            v = sacc[nt][2] + G10 + uu.x + ((w1 & 1) ? de1 : 0.f);
            if (w1 & 2) v -= 1e30f;
            sacc[nt][2] = v; mx1 = fmaxf(mx1, v);
            v = sacc[nt][3] + G11 + uu.y + ((w1 & 256) ? de1 : 0.f);
            if (w1 & 512) v -= 1e30f;
            sacc[nt][3] = v; mx1 = fmaxf(mx1, v);
        }
        // shuffle reductions also order G reads before P writes (alias)
#pragma unroll
        for (int o = 1; o < 4; o <<= 1) {
            mx0 = fmaxf(mx0, __shfl_xor_sync(0xffffffffu, mx0, o));
            mx1 = fmaxf(mx1, __shfl_xor_sync(0xffffffffu, mx1, o));
        }
        float nm0 = fmaxf(rmax[0], mx0);
        float nm1 = fmaxf(rmax[1], mx1);
        float corr0 = __expf(rmax[0] - nm0);
        float corr1 = __expf(rmax[1] - nm1);
        rmax[0] = nm0; rmax[1] = nm1;

        float sum0 = 0.f, sum1 = 0.f;
#pragma unroll
        for (int nt = 0; nt < 8; nt++) {
            float p0 = __expf(sacc[nt][0] - nm0);
            float p1 = __expf(sacc[nt][1] - nm0);
            float p2 = __expf(sacc[nt][2] - nm1);
            float p3 = __expf(sacc[nt][3] - nm1);
            sum0 += p0 + p1; sum1 += p2 + p3;
            Pwp[grp * 36 + nt * 4 + thr] = pk2(p0, p1);
            Pwp[(grp + 8) * 36 + nt * 4 + thr] = pk2(p2, p3);
        }
#pragma unroll
        for (int o = 1; o < 4; o <<= 1) {
            sum0 += __shfl_xor_sync(0xffffffffu, sum0, o);
            sum1 += __shfl_xor_sync(0xffffffffu, sum1, o);
        }
        rsum[0] = rsum[0] * corr0 + sum0;
        rsum[1] = rsum[1] * corr1 + sum1;

        CP_WAIT1();          // V(j) ready (prefetch group for j+1 may remain)
        __syncthreads();

        // ---- O = O*corr + P @ V ----
#pragma unroll
        for (int nt = 0; nt < 8; nt++) {
            oacc[nt][0] *= corr0; oacc[nt][1] *= corr0;
            oacc[nt][2] *= corr1; oacc[nt][3] *= corr1;
        }
#pragma unroll
        for (int kc = 0; kc < 4; kc++) {
            unsigned a[4];
            ldsm_x4(a[0], a[1], a[2], a[3], &Pwp[rowA * 36 + kc * 8 + koA]);
#pragma unroll
            for (int p = 0; p < 4; p++) {
                unsigned v0, v1, v2, v3;
                ldsm_x4_t(v0, v1, v2, v3,
                          vsb + (kc * 16 + rowV) * 72 + p * 16 + colV8);
                mma_bf16(oacc[2 * p], a, v0, v1);
                mma_bf16(oacc[2 * p + 1], a, v2, v3);
            }
        }
    }

    // ---- write normalized output (bf16) ----
    float inv0 = 1.f / rsum[0];
    float inv1 = 1.f / rsum[1];
#pragma unroll
    for (int nt = 0; nt < 8; nt++) {
        int d2 = n * 32 + nt * 4 + thr;
        g_avb_u[((size_t)(i0 + r0) * 4 + b) * 512 + d2] =
            pk2(oacc[nt][0] * inv0, oacc[nt][1] * inv0);
        g_avb_u[((size_t)(i0 + r0 + 8) * 4 + b) * 512 + d2] =
            pk2(oacc[nt][2] * inv1, oacc[nt][3] * inv1);
    }
}

// ---------------------------------------------------------------------------
// Residual + LayerNorm: 2 rows per block, batched loads (MLP 2x).
// ---------------------------------------------------------------------------
__global__ __launch_bounds__(256) void ln_kernel(
    const float* __restrict__ hres, const float* __restrict__ gamma,
    const float* __restrict__ beta, float* __restrict__ out)
{
    __shared__ float4 xb4[2][256];
    __shared__ float red1[2][8], red2[2][8];
    const int row0 = blockIdx.x * 2;
    const int tid = threadIdx.x;

    float4 g4 = *(const float4*)(gamma + tid * 4);
    float4 b4 = *(const float4*)(beta + tid * 4);

    float s[2], s2[2];
#pragma unroll
    for (int rr = 0; rr < 2; rr++) {
        float4 a4 = *(const float4*)(g_ao + (size_t)(row0 + rr) * 1024 + tid * 4);
        float4 h4 = *(const float4*)(hres + (size_t)(row0 + rr) * 1024 + tid * 4);
        float4 x4 = make_float4(a4.x + h4.x, a4.y + h4.y, a4.z + h4.z, a4.w + h4.w);
        xb4[rr][tid] = x4;
        s[rr] = x4.x + x4.y + x4.z + x4.w;
        s2[rr] = x4.x * x4.x + x4.y * x4.y + x4.z * x4.z + x4.w * x4.w;
    }
#pragma unroll
    for (int o = 16; o; o >>= 1) {
#pragma unroll
        for (int rr = 0; rr < 2; rr++) {
            s[rr] += __shfl_xor_sync(0xffffffffu, s[rr], o);
            s2[rr] += __shfl_xor_sync(0xffffffffu, s2[rr], o);
        }
    }
    if ((tid & 31) == 0) {
#pragma unroll
        for (int rr = 0; rr < 2; rr++) {
            red1[rr][tid >> 5] = s[rr];
            red2[rr][tid >> 5] = s2[rr];
        }
    }
    __syncthreads();
#pragma unroll
    for (int rr = 0; rr < 2; rr++) {
        float tot = 0.f, tot2 = 0.f;
#pragma unroll
        for (int k = 0; k < 8; k++) { tot += red1[rr][k]; tot2 += red2[rr][k]; }
        const float mean = tot * (1.f / 1024.f);
        const float var = tot2 * (1.f / 1024.f) - mean * mean;
        const float inv = rsqrtf(var + LN_EPS);
        float4 xx = xb4[rr][tid];
        float4 o4;
        o4.x = (xx.x - mean) * inv * g4.x + b4.x;
        o4.y = (xx.y - mean) * inv * g4.y + b4.y;
        o4.z = (xx.z - mean) * inv * g4.z + b4.z;
        o4.w = (xx.w - mean) * inv * g4.w + b4.w;
        *(float4*)(out + (size_t)(row0 + rr) * 1024 + tid * 4) = o4;
    }
}

// ---------------------------------------------------------------------------
extern "C" void kernel_launch(void* const* d_in, const int* in_sizes, int n_in,
                              void* d_out, int out_size)
{
    const float* rwb       = (const float*)d_in[0];
    const float* rsb       = (const float*)d_in[1];
    const float* rrb       = (const float*)d_in[2];
    const float* seg_embed = (const float*)d_in[3];
    const float* h         = (const float*)d_in[4];
    const float* r         = (const float*)d_in[5];
    const float* mems      = (const float*)d_in[6];
    const float* seg_mat   = (const float*)d_in[7];
    const float* attn_mask = (const float*)d_in[8];
    const float* wq        = (const float*)d_in[9];
    const float* wk        = (const float*)d_in[10];
    const float* wv        = (const float*)d_in[11];
    const float* wr        = (const float*)d_in[12];
    const float* wo        = (const float*)d_in[13];
    const float* gamma     = (const float*)d_in[14];
    const float* beta      = (const float*)d_in[15];

    cudaFuncSetAttribute(attn_kernel, cudaFuncAttributeMaxDynamicSharedMemorySize, ATT_SMEM_BYTES);
    cudaFuncSetAttribute(proj_mma, cudaFuncAttributeMaxDynamicSharedMemorySize, PROJ_SMEM);
    cudaFuncSetAttribute(out_mma, cudaFuncAttributeMaxDynamicSharedMemorySize, OUT_SMEM);

    prep_kernel<<<21504, 256>>>(mems, h, r, wo, seg_mat, attn_mask, wq, wk, wv, wr);
    proj_mma<<<dim3(8, 128), 256, PROJ_SMEM>>>();
    post_kernel<<<1536, 512>>>(rsb, seg_embed, rwb, rrb);
    attn_kernel<<<dim3(64, 4), 256, ATT_SMEM_BYTES>>>();
    out_mma<<<dim3(8, 32), 256, OUT_SMEM>>>();
    ln_kernel<<<1024, 256>>>(h, gamma, beta, (float*)d_out);
}

// round 16
// speedup vs baseline: 1.0041x; 1.0041x over previous
#include <cuda_runtime.h>
#include <cuda_bf16.h>
#include <math.h>

// Problem constants
#define QLEN 512
#define MLEN 512
#define KLEN 1024
#define RLEN 1536
#define BATCH 4
#define DM 1024
#define NH 16
#define DH 64
#define SCALE 0.125f
#define LN_EPS 1e-3f

// Scratch (device globals).  "_u" arrays hold packed bf16 pairs.
__device__ unsigned g_ab_u [10240 * 512];  // [mems(2048); h(2048); r(6144)]
__device__ unsigned g_wpk_u[4 * 1024 * 512]; // proj weights [w][n][k2] (k-contig)
__device__ unsigned g_wob_u[1024 * 512];   // wo bf16 [h][1024]
__device__ unsigned g_qb_u [2048 * 512];   // q_head bf16
__device__ unsigned g_kb_u [4096 * 512];   // k_head bf16 (pre-scaled by SCALE)
__device__ unsigned g_vb_u [4096 * 512];   // v_head bf16
__device__ unsigned g_krb_u[6144 * 512];   // k_r bf16 (pre-scaled by SCALE)
__device__ unsigned g_avb_u[2048 * 512];   // attn_vec bf16
__device__ float g_e [512 * 4 * 16];       // de = SCALE*(e1-e0) [i][b][n]
__device__ float g_u [4096 * 16];          // rwb·k_scaled
__device__ float g_t [6144 * 16];          // rrb·kr_scaled
__device__ unsigned char g_code[4 * 512 * 1024]; // [b][i][j]
__device__ float g_ao[2048 * 1024];        // attn_out (pre-LN, fp32)

// ---------------------------------------------------------------------------
// helpers
// ---------------------------------------------------------------------------
__device__ __forceinline__ unsigned pk2(float lo, float hi) {
    unsigned r;
    asm("cvt.rn.bf16x2.f32 %0, %1, %2;" : "=r"(r) : "f"(hi), "f"(lo));
    return r;
}
__device__ __forceinline__ float bf_lo(unsigned u) { return __uint_as_float(u << 16); }
__device__ __forceinline__ float bf_hi(unsigned u) { return __uint_as_float(u & 0xffff0000u); }

__device__ __forceinline__ void mma_bf16(float* d, const unsigned* a,
                                         unsigned b0, unsigned b1) {
    asm volatile(
        "mma.sync.aligned.m16n8k16.row.col.f32.bf16.bf16.f32 "
        "{%0,%1,%2,%3}, {%4,%5,%6,%7}, {%8,%9}, {%0,%1,%2,%3};\n"
        : "+f"(d[0]), "+f"(d[1]), "+f"(d[2]), "+f"(d[3])
        : "r"(a[0]), "r"(a[1]), "r"(a[2]), "r"(a[3]), "r"(b0), "r"(b1));
}

__device__ __forceinline__ void cpa16(void* dst, const void* src) {
    unsigned d = (unsigned)__cvta_generic_to_shared(dst);
    asm volatile("cp.async.cg.shared.global [%0], [%1], 16;\n" :: "r"(d), "l"(src));
}
#define CP_COMMIT() asm volatile("cp.async.commit_group;\n")
#define CP_WAIT0()  asm volatile("cp.async.wait_group 0;\n")
#define CP_WAIT1()  asm volatile("cp.async.wait_group 1;\n")
#define CP_WAIT2()  asm volatile("cp.async.wait_group 2;\n")

__device__ __forceinline__ void ldsm_x4(unsigned& r0, unsigned& r1,
                                        unsigned& r2, unsigned& r3, const void* p) {
    unsigned a = (unsigned)__cvta_generic_to_shared(p);
    asm volatile("ldmatrix.sync.aligned.m8n8.x4.shared.b16 {%0,%1,%2,%3}, [%4];"
                 : "=r"(r0), "=r"(r1), "=r"(r2), "=r"(r3) : "r"(a));
}
__device__ __forceinline__ void ldsm_x4_t(unsigned& r0, unsigned& r1,
                                          unsigned& r2, unsigned& r3, const void* p) {
    unsigned a = (unsigned)__cvta_generic_to_shared(p);
    asm volatile("ldmatrix.sync.aligned.m8n8.x4.trans.shared.b16 {%0,%1,%2,%3}, [%4];"
                 : "=r"(r0), "=r"(r1), "=r"(r2), "=r"(r3) : "r"(a));
}

// 4-panel ring slab index for kr/tb (panel = absolute row / 64)
#define SLAB4(m) (((((m) >> 6) & 3) << 6) + ((m) & 63))

// ---------------------------------------------------------------------------
// prep: fp32->bf16 casts + code bytes + weight pack (fused).
// bid [0,11264): cast ; [11264,19456): code ; [19456,21504): pack
// ---------------------------------------------------------------------------
__global__ __launch_bounds__(256) void prep_kernel(
    const float* __restrict__ mems, const float* __restrict__ h,
    const float* __restrict__ r, const float* __restrict__ wo,
    const float* __restrict__ seg_mat, const float* __restrict__ attn_mask,
    const float* __restrict__ wq, const float* __restrict__ wk,
    const float* __restrict__ wv, const float* __restrict__ wr)
{
    __shared__ unsigned tile[32][33];
    int bid = blockIdx.x;
    if (bid < 11264) {
        int idx = bid * 256 + threadIdx.x;
        int row = idx >> 8, p4 = idx & 255;
        const float* src;
        unsigned* dst;
        if (row < 2048)      { src = mems + (size_t)row * 1024;          dst = g_ab_u + (size_t)row * 512; }
        else if (row < 4096) { src = h + (size_t)(row - 2048) * 1024;    dst = g_ab_u + (size_t)row * 512; }
        else if (row < 10240){ src = r + (size_t)(row - 4096) * 1024;    dst = g_ab_u + (size_t)row * 512; }
        else                 { src = wo + (size_t)(row - 10240) * 1024;  dst = g_wob_u + (size_t)(row - 10240) * 512; }
        float4 v = *(const float4*)(src + p4 * 4);
        uint2 o;
        o.x = pk2(v.x, v.y);
        o.y = pk2(v.z, v.w);
        *(uint2*)(dst + p4 * 2) = o;
    } else if (bid < 19456) {
        int idx = (bid - 11264) * 256 + threadIdx.x;
        int b = idx & 3;
        int ij = idx >> 2;
        unsigned char c = (seg_mat[(size_t)idx * 2 + 1] != 0.f) ? 1 : 0;
        if (attn_mask[idx] != 0.f) c |= 2;
        g_code[((size_t)b << 19) + ij] = c;
    } else {
        // weight pack: fp32 [k][n] -> bf16 pairs [w][n][k2]
        int pb = bid - 19456;                // < 2048
        int w = pb >> 9;
        int rem = pb & 511;
        int k2base = (rem & 15) * 32;
        int nnbase = (rem >> 4) * 32;
        const float* W = (w == 0) ? wq : (w == 1) ? wk : (w == 2) ? wv : wr;
        const int tx = threadIdx.x & 31, ty = threadIdx.x >> 5;
#pragma unroll
        for (int i = 0; i < 4; i++) {
            int k2 = k2base + ty + 8 * i;
            tile[ty + 8 * i][tx] = pk2(W[(size_t)(2 * k2) * 1024 + nnbase + tx],
                                       W[(size_t)(2 * k2 + 1) * 1024 + nnbase + tx]);
        }
        __syncthreads();
#pragma unroll
        for (int i = 0; i < 4; i++) {
            int nn = nnbase + ty + 8 * i;
            g_wpk_u[(size_t)w * 524288 + (size_t)nn * 512 + k2base + tx] = tile[tx][ty + 8 * i];
        }
    }
}

// ---------------------------------------------------------------------------
// Projection GEMM (bf16, cp.async 4-stage, ldmatrix frags).
// ---------------------------------------------------------------------------
#define PSTG 4
#define PJA 3072
#define PROJ_SMEM ((PSTG * 2 * PJA) * 4)   // 98,304 B

__global__ __launch_bounds__(256, 2) void proj_mma()
{
    extern __shared__ unsigned psm[];
    unsigned* Asm = psm;
    unsigned* Bsm = psm + PSTG * PJA;

    const int rowbase = blockIdx.y * 128;
    const int colbase = blockIdx.x * 128;

    int abase, wsel, segbase;
    unsigned* Cu;
    float csc;
    if (rowbase < 2048)        { wsel = 0; segbase = 0;     abase = 2048; Cu = g_qb_u;  csc = 1.f;   }
    else if (rowbase < 6144)   { wsel = 1; segbase = 2048;  abase = 0;    Cu = g_kb_u;  csc = SCALE; }
    else if (rowbase < 10240)  { wsel = 2; segbase = 6144;  abase = 0;    Cu = g_vb_u;  csc = 1.f;   }
    else                       { wsel = 3; segbase = 10240; abase = 4096; Cu = g_krb_u; csc = SCALE; }
    const int crb = rowbase - segbase;

    const int tid = threadIdx.x;
    const int lane = tid & 31, warp = tid >> 5;
    const int wm = warp & 3, wn = warp >> 2;
    const int grp = lane >> 2, thr = lane & 3;
    const int rowA = (lane & 7) + (lane & 8);
    const int koA  = (lane & 16) >> 2;
    const int rowB = (lane & 7) + ((lane & 16) >> 1);
    const int kB   = (lane & 8) >> 1;

    const int arw = tid >> 1;
    const int asub = tid & 1;
    const unsigned* asrc = g_ab_u + (size_t)(abase + crb + arw) * 512 + asub * 8;
    const unsigned* bsrc = g_wpk_u + (size_t)wsel * 524288 + (size_t)(colbase + arw) * 512 + asub * 8;

    float acc[2][8][4];
#pragma unroll
    for (int mf = 0; mf < 2; mf++)
#pragma unroll
        for (int nf = 0; nf < 8; nf++)
#pragma unroll
            for (int q = 0; q < 4; q++) acc[mf][nf][q] = 0.f;

#define PROJ_ISSUE(it)                                                          \
    {                                                                           \
        int s_ = (it) & 3;                                                      \
        int k2base_ = (it) * 16;                                                \
        unsigned* ad = Asm + s_ * PJA + asub * 1536 + arw * 12;                 \
        cpa16(ad,     asrc + k2base_);                                          \
        cpa16(ad + 4, asrc + k2base_ + 4);                                      \
        unsigned* bd = Bsm + s_ * PJA + asub * 1536 + arw * 12;                 \
        cpa16(bd,     bsrc + k2base_);                                          \
        cpa16(bd + 4, bsrc + k2base_ + 4);                                      \
        CP_COMMIT();                                                            \
    }

    PROJ_ISSUE(0);
    PROJ_ISSUE(1);
    PROJ_ISSUE(2);

    for (int it = 0; it < 32; it++) {
        if (it >= 30) { CP_WAIT0(); } else { CP_WAIT2(); }
        __syncthreads();
        if (it + 3 < 32) PROJ_ISSUE(it + 3);
        const unsigned* Ast = Asm + (it & 3) * PJA;
        const unsigned* Bst = Bsm + (it & 3) * PJA;
#pragma unroll
        for (int s = 0; s < 2; s++) {
            const unsigned* As_ = Ast + s * 1536;
            const unsigned* Bs_ = Bst + s * 1536;
            unsigned a[2][4], bb[8][2];
#pragma unroll
            for (int mf = 0; mf < 2; mf++)
                ldsm_x4(a[mf][0], a[mf][1], a[mf][2], a[mf][3],
                        As_ + (wm * 32 + mf * 16 + rowA) * 12 + koA);
#pragma unroll
            for (int nf0 = 0; nf0 < 8; nf0 += 2) {
                unsigned t0, t1, t2, t3;
                ldsm_x4(t0, t1, t2, t3, Bs_ + (wn * 64 + nf0 * 8 + rowB) * 12 + kB);
                bb[nf0][0] = t0; bb[nf0][1] = t1;
                bb[nf0 + 1][0] = t2; bb[nf0 + 1][1] = t3;
            }
#pragma unroll
            for (int mf = 0; mf < 2; mf++)
#pragma unroll
                for (int nf = 0; nf < 8; nf++)
                    mma_bf16(acc[mf][nf], a[mf], bb[nf][0], bb[nf][1]);
        }
    }
#pragma unroll
    for (int mf = 0; mf < 2; mf++)
#pragma unroll
        for (int nf = 0; nf < 8; nf++) {
            int rr = crb + wm * 32 + mf * 16 + grp;
            int c2 = (colbase >> 1) + wn * 32 + nf * 4 + thr;
            Cu[(size_t)rr * 512 + c2] = pk2(acc[mf][nf][0] * csc, acc[mf][nf][1] * csc);
            Cu[(size_t)(rr + 8) * 512 + c2] = pk2(acc[mf][nf][2] * csc, acc[mf][nf][3] * csc);
        }
#undef PROJ_ISSUE
}

// ---------------------------------------------------------------------------
// Output GEMM (bf16, 4-stage, ldmatrix frags): g_ao = g_avb @ wob^T.
// 64x128 tiles, grid (8,32)=256 blocks. 8 warps = 2m x 4n, warp tile 32x32.
// ---------------------------------------------------------------------------
#define OJS 4608
#define OUT_SMEM ((PSTG * OJS) * 4)    // 73,728 B

__global__ __launch_bounds__(256, 2) void out_mma()
{
    extern __shared__ unsigned psm[];

    const int rowbase = blockIdx.y * 64;
    const int colbase = blockIdx.x * 128;
    const int tid = threadIdx.x;
    const int lane = tid & 31, warp = tid >> 5;
    const int wm = warp & 1, wn = warp >> 1;
    const int grp = lane >> 2, thr = lane & 3;
    const int rowA = (lane & 7) + (lane & 8);
    const int koA  = (lane & 16) >> 2;
    const int rowB = (lane & 7) + ((lane & 16) >> 1);
    const int kB   = (lane & 8) >> 1;

    float acc[2][4][4];
#pragma unroll
    for (int mf = 0; mf < 2; mf++)
#pragma unroll
        for (int nf = 0; nf < 4; nf++)
#pragma unroll
            for (int q = 0; q < 4; q++) acc[mf][nf][q] = 0.f;

#define OUT_ISSUE(it)                                                           \
    {                                                                           \
        int s_ = (it) & 3;                                                      \
        int k2base_ = (it) * 16;                                                \
        {                                                                       \
            int row_ = tid >> 2;                                                \
            int sub_ = (tid & 2) >> 1;                                          \
            int half_ = tid & 1;                                                \
            cpa16(psm + s_ * OJS + sub_ * 768 + row_ * 12 + half_ * 4,          \
                  g_avb_u + (size_t)(rowbase + row_) * 512 + k2base_ +          \
                  sub_ * 8 + half_ * 4);                                        \
        }                                                                       \
        for (int t_ = tid; t_ < 512; t_ += 256) {                               \
            int row_ = t_ >> 2;                                                 \
            int sub_ = (t_ & 2) >> 1;                                           \
            int half_ = t_ & 1;                                                 \
            cpa16(psm + s_ * OJS + 1536 + sub_ * 1536 + row_ * 12 + half_ * 4,  \
                  g_wob_u + (size_t)(colbase + row_) * 512 + k2base_ +          \
                  sub_ * 8 + half_ * 4);                                        \
        }                                                                       \
        CP_COMMIT();                                                            \
    }

    OUT_ISSUE(0);
    OUT_ISSUE(1);
    OUT_ISSUE(2);

    for (int it = 0; it < 32; it++) {
        if (it >= 30) { CP_WAIT0(); } else { CP_WAIT2(); }
        __syncthreads();
        if (it + 3 < 32) OUT_ISSUE(it + 3);
        const unsigned* stg = psm + (it & 3) * OJS;
#pragma unroll
        for (int s = 0; s < 2; s++) {
            const unsigned* As_ = stg + s * 768;
            const unsigned* Bs_ = stg + 1536 + s * 1536;
            unsigned a[2][4], bb[4][2];
#pragma unroll
            for (int mf = 0; mf < 2; mf++)
                ldsm_x4(a[mf][0], a[mf][1], a[mf][2], a[mf][3],
                        As_ + (wm * 32 + mf * 16 + rowA) * 12 + koA);
#pragma unroll
            for (int nf0 = 0; nf0 < 4; nf0 += 2) {
                unsigned t0, t1, t2, t3;
                ldsm_x4(t0, t1, t2, t3, Bs_ + (wn * 32 + nf0 * 8 + rowB) * 12 + kB);
                bb[nf0][0] = t0; bb[nf0][1] = t1;
                bb[nf0 + 1][0] = t2; bb[nf0 + 1][1] = t3;
            }
#pragma unroll
            for (int mf = 0; mf < 2; mf++)
#pragma unroll
                for (int nf = 0; nf < 4; nf++)
                    mma_bf16(acc[mf][nf], a[mf], bb[nf][0], bb[nf][1]);
        }
    }
#pragma unroll
    for (int mf = 0; mf < 2; mf++)
#pragma unroll
        for (int nf = 0; nf < 4; nf++) {
            int rr = rowbase + wm * 32 + mf * 16 + grp;
            int cc = colbase + wn * 32 + nf * 8 + thr * 2;
            *(float2*)&g_ao[(size_t)rr * 1024 + cc] = make_float2(acc[mf][nf][0], acc[mf][nf][1]);
            *(float2*)&g_ao[(size_t)(rr + 8) * 1024 + cc] = make_float2(acc[mf][nf][2], acc[mf][nf][3]);
        }
#undef OUT_ISSUE
}

// ---------------------------------------------------------------------------
// post: 8 rows per block, warp n handles head n, fully coalesced.
// ---------------------------------------------------------------------------
__global__ __launch_bounds__(512) void post_kernel(
    const float* __restrict__ rsb, const float* __restrict__ seg_embed,
    const float* __restrict__ rwb, const float* __restrict__ rrb)
{
    const int n = threadIdx.x >> 5, lane = threadIdx.x & 31;
    if (blockIdx.x < 256) {
        const int rbase = blockIdx.x * 8;       // rows (i*4+b)
        float2 rb = *(const float2*)(rsb + n * 64 + 2 * lane);
        float2 s0 = *(const float2*)(seg_embed + n * 64 + 2 * lane);
        float2 s1 = *(const float2*)(seg_embed + 1024 + n * 64 + 2 * lane);
        unsigned uu[8];
#pragma unroll
        for (int rr = 0; rr < 8; rr++)
            uu[rr] = g_qb_u[(size_t)(rbase + rr) * 512 + n * 32 + lane];
#pragma unroll
        for (int rr = 0; rr < 8; rr++) {
            float q1 = bf_lo(uu[rr]) + rb.x;
            float q2 = bf_hi(uu[rr]) + rb.y;
            float p0 = q1 * s0.x + q2 * s0.y;
            float p1 = q1 * s1.x + q2 * s1.y;
#pragma unroll
            for (int o = 16; o; o >>= 1) {
                p0 += __shfl_xor_sync(0xffffffffu, p0, o);
                p1 += __shfl_xor_sync(0xffffffffu, p1, o);
            }
            if (lane == 0) g_e[(size_t)(rbase + rr) * 16 + n] = (p1 - p0) * SCALE;
        }
    } else {
        int rbase = (blockIdx.x - 256) * 8;
        const unsigned* src;
        const float* bias;
        float* dst;
        if (rbase < 4096) {
            src = g_kb_u + (size_t)rbase * 512;
            bias = rwb; dst = g_u + (size_t)rbase * 16;
        } else {
            src = g_krb_u + (size_t)(rbase - 4096) * 512;
            bias = rrb; dst = g_t + (size_t)(rbase - 4096) * 16;
        }
        float2 rb = *(const float2*)(bias + n * 64 + 2 * lane);
        unsigned uu[8];
#pragma unroll
        for (int rr = 0; rr < 8; rr++)
            uu[rr] = src[(size_t)rr * 512 + n * 32 + lane];
#pragma unroll
        for (int rr = 0; rr < 8; rr++) {
            float p = bf_lo(uu[rr]) * rb.x + bf_hi(uu[rr]) * rb.y;
#pragma unroll
            for (int o = 16; o; o >>= 1) p += __shfl_xor_sync(0xffffffffu, p, o);
            if (lane == 0) dst[(size_t)rr * 16 + n] = p;
        }
    }
}

// ---------------------------------------------------------------------------
// Fused attention (R13 design): warp-local, ldmatrix frags, software-pipelined
// j-loop, 4-panel kr ring, P aliased onto Gw.
// smem 110,848 B -> 2 blocks/SM.
// ---------------------------------------------------------------------------
#define ATT_SMEM_BYTES (27712 * 4)

__global__ __launch_bounds__(256, 2) void attn_kernel()
{
    extern __shared__ unsigned smu[];
    unsigned* ksu2 = smu;                       // 2 x [64 x 36]
    unsigned* kru  = smu + 4608;                // 256 x 36 (4-panel ring)
    unsigned* vsu  = smu + 13824;               // 64 x 36
    float* Gw  = (float*)(smu + 16128);         // 8 x [16 x 88]  (P aliases)
    float* ub  = (float*)(smu + 27392);         // 64
    float* tb2 = (float*)(smu + 27456);         // 256 (4-panel ring)
    const __nv_bfloat16* vsb = (const __nv_bfloat16*)vsu;  // row stride 72 bf16

    const int b = blockIdx.x >> 4, n = blockIdx.x & 15;
    const int i0 = blockIdx.y * 128;
    const int tid = threadIdx.x;
    const int wm = tid >> 5, lane = tid & 31;
    const int grp = lane >> 2, thr = lane & 3;
    const int r0 = wm * 16 + grp;               // local rows r0, r0+8

    float* Gwp = Gw + wm * (16 * 88);
    unsigned* Pwp = (unsigned*)Gwp;             // alias (rows stride 36 u32)

    const int row16 = (lane & 7) + ((lane & 16) >> 1);  // B-frag rows
    const int koB   = (lane & 8) >> 1;
    const int rowA  = (lane & 7) + (lane & 8);          // A-frag rows
    const int koA   = (lane & 16) >> 2;
    const int rowV  = lane & 15;
    const int colV8 = (lane & 16) >> 1;

    // ---- q fragments straight from global bf16 ----
    unsigned qa[4][4];
#pragma unroll
    for (int kc = 0; kc < 4; kc++) {
        size_t b0 = ((size_t)(i0 + r0) * 4 + b) * 512 + n * 32 + kc * 8;
        size_t b1 = ((size_t)(i0 + r0 + 8) * 4 + b) * 512 + n * 32 + kc * 8;
        qa[kc][0] = g_qb_u[b0 + thr];
        qa[kc][1] = g_qb_u[b1 + thr];
        qa[kc][2] = g_qb_u[b0 + thr + 4];
        qa[kc][3] = g_qb_u[b1 + thr + 4];
    }

    float de0 = g_e[((size_t)(i0 + r0) * 4 + b) * 16 + n];
    float de1 = g_e[((size_t)(i0 + r0 + 8) * 4 + b) * 16 + n];

    float oacc[8][4];
#pragma unroll
    for (int nt = 0; nt < 8; nt++)
#pragma unroll
        for (int q = 0; q < 4; q++) oacc[nt][q] = 0.f;
    float rmax[2] = {-3.0e38f, -3.0e38f};
    float rsum[2] = {0.f, 0.f};

    const unsigned char* codeRow0 = g_code + ((size_t)b << 19) + (size_t)(i0 + r0) * 1024;
    const unsigned char* codeRow1 = codeRow0 + 8 * 1024;

    // ---- prologue: K0 + kr window0 (3 panels) ----
    const int base0 = 384 - i0;
    for (int t = tid; t < 512; t += 256) {
        int row = t >> 3, c = (t & 7) * 4;
        cpa16(&ksu2[row * 36 + c],
              g_kb_u + ((size_t)row * 4 + b) * 512 + n * 32 + c);
    }
    for (int t = tid; t < 192 * 8; t += 256) {
        int o = t >> 3, c = (t & 7) * 4;
        cpa16(&kru[SLAB4(base0 + o) * 36 + c],
              g_krb_u + ((size_t)(base0 + o) * 4 + b) * 512 + n * 32 + c);
    }
    CP_COMMIT();
    if (tid < 192)
        tb2[SLAB4(base0 + tid)] = g_t[((size_t)(base0 + tid) * 4 + b) * 16 + n];

    for (int j0 = 0; j0 < KLEN; j0 += 64) {
        const int ji = j0 >> 6;
        const int base = j0 - i0 + 384;
        __syncthreads();                         // prior-iter reads done
        // ---- issue V(j) ----
        for (int t = tid; t < 512; t += 256) {
            int row = t >> 3, c = (t & 7) * 4;
            cpa16(&vsu[row * 36 + c],
                  g_vb_u + ((size_t)(j0 + row) * 4 + b) * 512 + n * 32 + c);
        }
        CP_COMMIT();
        // ---- issue K(j+1) + kr-panel(j+1) (prefetch one iter ahead) ----
        if (j0 + 64 < KLEN) {
            unsigned* ksn = ksu2 + ((ji + 1) & 1) * 2304;
            for (int t = tid; t < 512; t += 256) {
                int row = t >> 3, c = (t & 7) * 4;
                cpa16(&ksn[row * 36 + c],
                      g_kb_u + ((size_t)(j0 + 64 + row) * 4 + b) * 512 + n * 32 + c);
            }
            for (int t = tid; t < 512; t += 256) {
                int o = 192 + (t >> 3), c = (t & 7) * 4;
                cpa16(&kru[SLAB4(base + o) * 36 + c],
                      g_krb_u + ((size_t)(base + o) * 4 + b) * 512 + n * 32 + c);
            }
        }
        CP_COMMIT();
        // ---- scalar ub(j) + tb panel(j+1) ----
        if (tid < 64) {
            ub[tid] = g_u[((size_t)(j0 + tid) * 4 + b) * 16 + n];
        } else if (tid < 128 && j0 + 64 < KLEN) {
            int o = 192 + (tid - 64);
            tb2[SLAB4(base + o)] = g_t[((size_t)(base + o) * 4 + b) * 16 + n];
        }
        CP_WAIT2();          // completes group with K(j)/kr(j) (issued iter j-1)
        __syncthreads();

        // ---- S = q @ k^T ----
        const unsigned* ksc = ksu2 + (ji & 1) * 2304;
        float sacc[8][4];
#pragma unroll
        for (int nt = 0; nt < 8; nt++)
#pragma unroll
            for (int q = 0; q < 4; q++) sacc[nt][q] = 0.f;
#pragma unroll
        for (int kc = 0; kc < 4; kc++) {
#pragma unroll
            for (int p = 0; p < 4; p++) {
                unsigned k0, k1, k2, k3;
                ldsm_x4(k0, k1, k2, k3, &ksc[(16 * p + row16) * 36 + kc * 8 + koB]);
                mma_bf16(sacc[2 * p], qa[kc], k0, k1);
                mma_bf16(sacc[2 * p + 1], qa[kc], k2, k3);
            }
        }

        // ---- per-warp band G (16 x 80), +t folded at store (float2) ----
        const int woff = 112 - wm * 16;
#pragma unroll
        for (int p = 0; p < 5; p++) {
            int o = woff + 16 * p + row16;
            int srow = SLAB4(base + o);
            float ga[4] = {0.f, 0.f, 0.f, 0.f};
            float gb[4] = {0.f, 0.f, 0.f, 0.f};
#pragma unroll
            for (int kc = 0; kc < 4; kc++) {
                unsigned k0, k1, k2, k3;
                ldsm_x4(k0, k1, k2, k3, &kru[srow * 36 + kc * 8 + koB]);
                mma_bf16(ga, qa[kc], k0, k1);
                mma_bf16(gb, qa[kc], k2, k3);
            }
            int g0 = 16 * p + 2 * thr;
            int oA = woff + g0;
            float2 tA = *(float2*)&tb2[SLAB4(base + oA)];
            int oB = oA + 8;
            float2 tB = *(float2*)&tb2[SLAB4(base + oB)];
            *(float2*)&Gwp[grp * 88 + g0]           = make_float2(ga[0] + tA.x, ga[1] + tA.y);
            *(float2*)&Gwp[(grp + 8) * 88 + g0]     = make_float2(ga[2] + tA.x, ga[3] + tA.y);
            *(float2*)&Gwp[grp * 88 + g0 + 8]       = make_float2(gb[0] + tB.x, gb[1] + tB.y);
            *(float2*)&Gwp[(grp + 8) * 88 + g0 + 8] = make_float2(gb[2] + tB.x, gb[3] + tB.y);
        }
        __syncwarp();

        // ---- assemble logits, warp-local row maxes ----
        float mx0 = -3.0e38f, mx1 = -3.0e38f;
#pragma unroll
        for (int nt = 0; nt < 8; nt++) {
            int c = nt * 8 + 2 * thr;
            int gi  = c - grp + 16;
            int gi2 = c - grp + 8;
            float G00, G01, G10, G11;
            if ((grp & 1) == 0) {
                float2 fa = *(float2*)&Gwp[grp * 88 + gi];
                float2 fb = *(float2*)&Gwp[(grp + 8) * 88 + gi2];
                G00 = fa.x; G01 = fa.y; G10 = fb.x; G11 = fb.y;
            } else {
                G00 = Gwp[grp * 88 + gi];
                G01 = Gwp[grp * 88 + gi + 1];
                G10 = Gwp[(grp + 8) * 88 + gi2];
                G11 = Gwp[(grp + 8) * 88 + gi2 + 1];
            }
            unsigned short w0 = *(const unsigned short*)(codeRow0 + j0 + c);
            unsigned short w1 = *(const unsigned short*)(codeRow1 + j0 + c);
            float2 uu = *(float2*)&ub[c];
            float v;
            v = sacc[nt][0] + G00 + uu.x + ((w0 & 1) ? de0 : 0.f);
            if (w0 & 2) v -= 1e30f;
            sacc[nt][0] = v; mx0 = fmaxf(mx0, v);
            v = sacc[nt][1] + G01 + uu.y + ((w0 & 256) ? de0 : 0.f);
            if (w0 & 512) v -= 1e30f;
            sacc[nt][1] = v; mx0 = fmaxf(mx0, v);
            v = sacc[nt][2] + G10 + uu.x + ((w1 & 1) ? de1 : 0.f);
            if (w1 & 2) v -= 1e30f;
            sacc[nt][2] = v; mx1 = fmaxf(mx1, v);
            v = sacc[nt][3] + G11 + uu.y + ((w1 & 256) ? de1 : 0.f);
            if (w1 & 512) v -= 1e30f;
            sacc[nt][3] = v; mx1 = fmaxf(mx1, v);
        }
        // shuffle reductions also order G reads before P writes (alias)
#pragma unroll
        for (int o = 1; o < 4; o <<= 1) {
            mx0 = fmaxf(mx0, __shfl_xor_sync(0xffffffffu, mx0, o));
            mx1 = fmaxf(mx1, __shfl_xor_sync(0xffffffffu, mx1, o));
        }
        float nm0 = fmaxf(rmax[0], mx0);
        float nm1 = fmaxf(rmax[1], mx1);
        float corr0 = __expf(rmax[0] - nm0);
        float corr1 = __expf(rmax[1] - nm1);
        rmax[0] = nm0; rmax[1] = nm1;

        float sum0 = 0.f, sum1 = 0.f;
#pragma unroll
        for (int nt = 0; nt < 8; nt++) {
            float p0 = __expf(sacc[nt][0] - nm0);
            float p1 = __expf(sacc[nt][1] - nm0);
            float p2 = __expf(sacc[nt][2] - nm1);
            float p3 = __expf(sacc[nt][3] - nm1);
            sum0 += p0 + p1; sum1 += p2 + p3;
            Pwp[grp * 36 + nt * 4 + thr] = pk2(p0, p1);
            Pwp[(grp + 8) * 36 + nt * 4 + thr] = pk2(p2, p3);
        }
#pragma unroll
        for (int o = 1; o < 4; o <<= 1) {
            sum0 += __shfl_xor_sync(0xffffffffu, sum0, o);
            sum1 += __shfl_xor_sync(0xffffffffu, sum1, o);
        }
        rsum[0] = rsum[0] * corr0 + sum0;
        rsum[1] = rsum[1] * corr1 + sum1;

        CP_WAIT1();          // V(j) ready (prefetch group for j+1 may remain)
        __syncthreads();

        // ---- O = O*corr + P @ V ----
#pragma unroll
        for (int nt = 0; nt < 8; nt++) {
            oacc[nt][0] *= corr0; oacc[nt][1] *= corr0;
            oacc[nt][2] *= corr1; oacc[nt][3] *= corr1;
        }
#pragma unroll
        for (int kc = 0; kc < 4; kc++) {
            unsigned a[4];
            ldsm_x4(a[0], a[1], a[2], a[3], &Pwp[rowA * 36 + kc * 8 + koA]);
#pragma unroll
            for (int p = 0; p < 4; p++) {
                unsigned v0, v1, v2, v3;
                ldsm_x4_t(v0, v1, v2, v3,
                          vsb + (kc * 16 + rowV) * 72 + p * 16 + colV8);
                mma_bf16(oacc[2 * p], a, v0, v1);
                mma_bf16(oacc[2 * p + 1], a, v2, v3);
            }
        }
    }

    // ---- write normalized output (bf16) ----
    float inv0 = 1.f / rsum[0];
    float inv1 = 1.f / rsum[1];
#pragma unroll
    for (int nt = 0; nt < 8; nt++) {
        int d2 = n * 32 + nt * 4 + thr;
        g_avb_u[((size_t)(i0 + r0) * 4 + b) * 512 + d2] =
            pk2(oacc[nt][0] * inv0, oacc[nt][1] * inv0);
        g_avb_u[((size_t)(i0 + r0 + 8) * 4 + b) * 512 + d2] =
            pk2(oacc[nt][2] * inv1, oacc[nt][3] * inv1);
    }
}

// ---------------------------------------------------------------------------
// Residual + LayerNorm (single pass, float4)
// ---------------------------------------------------------------------------
__global__ __launch_bounds__(256) void ln_kernel(
    const float* __restrict__ hres, const float* __restrict__ gamma,
    const float* __restrict__ beta, float* __restrict__ out)
{
    __shared__ float4 xb4[256];
    __shared__ float red1[8], red2[8];
    const int row = blockIdx.x;
    const int tid = threadIdx.x;

    float4 a4 = *(const float4*)(g_ao + (size_t)row * 1024 + tid * 4);
    float4 h4 = *(const float4*)(hres + (size_t)row * 1024 + tid * 4);
    float4 x4 = make_float4(a4.x + h4.x, a4.y + h4.y, a4.z + h4.z, a4.w + h4.w);
    xb4[tid] = x4;
    float s = x4.x + x4.y + x4.z + x4.w;
    float s2 = x4.x * x4.x + x4.y * x4.y + x4.z * x4.z + x4.w * x4.w;
#pragma unroll
    for (int o = 16; o; o >>= 1) {
        s += __shfl_xor_sync(0xffffffffu, s, o);
        s2 += __shfl_xor_sync(0xffffffffu, s2, o);
    }
    if ((tid & 31) == 0) { red1[tid >> 5] = s; red2[tid >> 5] = s2; }
    __syncthreads();
    float tot = 0.f, tot2 = 0.f;
#pragma unroll
    for (int k = 0; k < 8; k++) { tot += red1[k]; tot2 += red2[k]; }
    const float mean = tot * (1.f / 1024.f);
    const float var = tot2 * (1.f / 1024.f) - mean * mean;
    const float inv = rsqrtf(var + LN_EPS);

    float4 g4 = *(const float4*)(gamma + tid * 4);
    float4 b4 = *(const float4*)(beta + tid * 4);
    float4 xx = xb4[tid];
    float4 o4;
    o4.x = (xx.x - mean) * inv * g4.x + b4.x;
    o4.y = (xx.y - mean) * inv * g4.y + b4.y;
    o4.z = (xx.z - mean) * inv * g4.z + b4.z;
    o4.w = (xx.w - mean) * inv * g4.w + b4.w;
    *(float4*)(out + (size_t)row * 1024 + tid * 4) = o4;
}

// ---------------------------------------------------------------------------
extern "C" void kernel_launch(void* const* d_in, const int* in_sizes, int n_in,
                              void* d_out, int out_size)
{
    const float* rwb       = (const float*)d_in[0];
    const float* rsb       = (const float*)d_in[1];
    const float* rrb       = (const float*)d_in[2];
    const float* seg_embed = (const float*)d_in[3];
    const float* h         = (const float*)d_in[4];
    const float* r         = (const float*)d_in[5];
    const float* mems      = (const float*)d_in[6];
    const float* seg_mat   = (const float*)d_in[7];
    const float* attn_mask = (const float*)d_in[8];
    const float* wq        = (const float*)d_in[9];
    const float* wk        = (const float*)d_in[10];
    const float* wv        = (const float*)d_in[11];
    const float* wr        = (const float*)d_in[12];
    const float* wo        = (const float*)d_in[13];
    const float* gamma     = (const float*)d_in[14];
    const float* beta      = (const float*)d_in[15];

    cudaFuncSetAttribute(attn_kernel, cudaFuncAttributeMaxDynamicSharedMemorySize, ATT_SMEM_BYTES);
    cudaFuncSetAttribute(proj_mma, cudaFuncAttributeMaxDynamicSharedMemorySize, PROJ_SMEM);
    cudaFuncSetAttribute(out_mma, cudaFuncAttributeMaxDynamicSharedMemorySize, OUT_SMEM);

    prep_kernel<<<21504, 256>>>(mems, h, r, wo, seg_mat, attn_mask, wq, wk, wv, wr);
    proj_mma<<<dim3(8, 128), 256, PROJ_SMEM>>>();
    post_kernel<<<1536, 512>>>(rsb, seg_embed, rwb, rrb);
    attn_kernel<<<dim3(64, 4), 256, ATT_SMEM_BYTES>>>();
    out_mma<<<dim3(8, 32), 256, OUT_SMEM>>>();
    ln_kernel<<<2048, 256>>>(h, gamma, beta, (float*)d_out);
}

// round 17
// speedup vs baseline: 1.0295x; 1.0253x over previous
#include <cuda_runtime.h>
#include <cuda_bf16.h>
#include <math.h>

// Problem constants
#define QLEN 512
#define MLEN 512
#define KLEN 1024
#define RLEN 1536
#define BATCH 4
#define DM 1024
#define NH 16
#define DH 64
#define SCALE 0.125f
#define LN_EPS 1e-3f

// Scratch (device globals).  "_u" arrays hold packed bf16 pairs.
__device__ unsigned g_ab_u [10240 * 512];  // [mems(2048); h(2048); r(6144)]
__device__ unsigned g_wpk_u[4 * 1024 * 512]; // proj weights [w][n][k2] (k-contig)
__device__ unsigned g_wob_u[1024 * 512];   // wo bf16 [h][1024]
__device__ unsigned g_qb_u [2048 * 512];   // q_head bf16
__device__ unsigned g_kb_u [4096 * 512];   // k_head bf16 (pre-scaled by SCALE)
__device__ unsigned g_vb_u [4096 * 512];   // v_head bf16
__device__ unsigned g_krb_u[6144 * 512];   // k_r bf16 (pre-scaled by SCALE)
__device__ unsigned g_avb_u[2048 * 512];   // attn_vec bf16
__device__ float g_e [512 * 4 * 16];       // de = SCALE*(e1-e0) [i][b][n]
__device__ float g_u [4096 * 16];          // rwb·k_scaled
__device__ float g_t [6144 * 16];          // rrb·kr_scaled
__device__ unsigned char g_code[4 * 512 * 1024]; // [b][i][j]
__device__ float g_ao[2048 * 1024];        // attn_out (pre-LN, fp32)

// ---------------------------------------------------------------------------
// helpers
// ---------------------------------------------------------------------------
__device__ __forceinline__ unsigned pk2(float lo, float hi) {
    unsigned r;
    asm("cvt.rn.bf16x2.f32 %0, %1, %2;" : "=r"(r) : "f"(hi), "f"(lo));
    return r;
}
__device__ __forceinline__ float bf_lo(unsigned u) { return __uint_as_float(u << 16); }
__device__ __forceinline__ float bf_hi(unsigned u) { return __uint_as_float(u & 0xffff0000u); }

__device__ __forceinline__ void mma_bf16(float* d, const unsigned* a,
                                         unsigned b0, unsigned b1) {
    asm volatile(
        "mma.sync.aligned.m16n8k16.row.col.f32.bf16.bf16.f32 "
        "{%0,%1,%2,%3}, {%4,%5,%6,%7}, {%8,%9}, {%0,%1,%2,%3};\n"
        : "+f"(d[0]), "+f"(d[1]), "+f"(d[2]), "+f"(d[3])
        : "r"(a[0]), "r"(a[1]), "r"(a[2]), "r"(a[3]), "r"(b0), "r"(b1));
}

__device__ __forceinline__ void cpa16(void* dst, const void* src) {
    unsigned d = (unsigned)__cvta_generic_to_shared(dst);
    asm volatile("cp.async.cg.shared.global [%0], [%1], 16;\n" :: "r"(d), "l"(src));
}
#define CP_COMMIT() asm volatile("cp.async.commit_group;\n")
#define CP_WAIT0()  asm volatile("cp.async.wait_group 0;\n")
#define CP_WAIT1()  asm volatile("cp.async.wait_group 1;\n")
#define CP_WAIT2()  asm volatile("cp.async.wait_group 2;\n")

__device__ __forceinline__ void ldsm_x4(unsigned& r0, unsigned& r1,
                                        unsigned& r2, unsigned& r3, const void* p) {
    unsigned a = (unsigned)__cvta_generic_to_shared(p);
    asm volatile("ldmatrix.sync.aligned.m8n8.x4.shared.b16 {%0,%1,%2,%3}, [%4];"
                 : "=r"(r0), "=r"(r1), "=r"(r2), "=r"(r3) : "r"(a));
}
__device__ __forceinline__ void ldsm_x4_t(unsigned& r0, unsigned& r1,
                                          unsigned& r2, unsigned& r3, const void* p) {
    unsigned a = (unsigned)__cvta_generic_to_shared(p);
    asm volatile("ldmatrix.sync.aligned.m8n8.x4.trans.shared.b16 {%0,%1,%2,%3}, [%4];"
                 : "=r"(r0), "=r"(r1), "=r"(r2), "=r"(r3) : "r"(a));
}

// 4-panel ring slab index for kr/tb (panel = absolute row / 64)
#define SLAB4(m) (((((m) >> 6) & 3) << 6) + ((m) & 63))

// ---------------------------------------------------------------------------
// prep: fp32->bf16 casts + code bytes + weight pack (fused).
// bid [0,11264): cast ; [11264,19456): code ; [19456,21504): pack
// ---------------------------------------------------------------------------
__global__ __launch_bounds__(256) void prep_kernel(
    const float* __restrict__ mems, const float* __restrict__ h,
    const float* __restrict__ r, const float* __restrict__ wo,
    const float* __restrict__ seg_mat, const float* __restrict__ attn_mask,
    const float* __restrict__ wq, const float* __restrict__ wk,
    const float* __restrict__ wv, const float* __restrict__ wr)
{
    __shared__ unsigned tile[32][33];
    int bid = blockIdx.x;
    if (bid < 11264) {
        int idx = bid * 256 + threadIdx.x;
        int row = idx >> 8, p4 = idx & 255;
        const float* src;
        unsigned* dst;
        if (row < 2048)      { src = mems + (size_t)row * 1024;          dst = g_ab_u + (size_t)row * 512; }
        else if (row < 4096) { src = h + (size_t)(row - 2048) * 1024;    dst = g_ab_u + (size_t)row * 512; }
        else if (row < 10240){ src = r + (size_t)(row - 4096) * 1024;    dst = g_ab_u + (size_t)row * 512; }
        else                 { src = wo + (size_t)(row - 10240) * 1024;  dst = g_wob_u + (size_t)(row - 10240) * 512; }
        float4 v = *(const float4*)(src + p4 * 4);
        uint2 o;
        o.x = pk2(v.x, v.y);
        o.y = pk2(v.z, v.w);
        *(uint2*)(dst + p4 * 2) = o;
    } else if (bid < 19456) {
        int idx = (bid - 11264) * 256 + threadIdx.x;
        int b = idx & 3;
        int ij = idx >> 2;
        unsigned char c = (seg_mat[(size_t)idx * 2 + 1] != 0.f) ? 1 : 0;
        if (attn_mask[idx] != 0.f) c |= 2;
        g_code[((size_t)b << 19) + ij] = c;
    } else {
        // weight pack: fp32 [k][n] -> bf16 pairs [w][n][k2]
        int pb = bid - 19456;                // < 2048
        int w = pb >> 9;
        int rem = pb & 511;
        int k2base = (rem & 15) * 32;
        int nnbase = (rem >> 4) * 32;
        const float* W = (w == 0) ? wq : (w == 1) ? wk : (w == 2) ? wv : wr;
        const int tx = threadIdx.x & 31, ty = threadIdx.x >> 5;
#pragma unroll
        for (int i = 0; i < 4; i++) {
            int k2 = k2base + ty + 8 * i;
            tile[ty + 8 * i][tx] = pk2(W[(size_t)(2 * k2) * 1024 + nnbase + tx],
                                       W[(size_t)(2 * k2 + 1) * 1024 + nnbase + tx]);
        }
        __syncthreads();
#pragma unroll
        for (int i = 0; i < 4; i++) {
            int nn = nnbase + ty + 8 * i;
            g_wpk_u[(size_t)w * 524288 + (size_t)nn * 512 + k2base + tx] = tile[tx][ty + 8 * i];
        }
    }
}

// ---------------------------------------------------------------------------
// Projection GEMM (bf16, cp.async 4-stage, ldmatrix frags) WITH fused bias
// reductions in the epilogue:
//   wsel 0 (q):  g_e[row][head] = SCALE*(q·ds + rsb·ds), ds = seg1-seg0
//   wsel 1 (k):  g_u[row][head] = SCALE*(k_fp32·rwb)     (k stored scaled)
//   wsel 3 (kr): g_t[row][head] = SCALE*(kr_fp32·rrb)
// Exactness: block col-slice = 2 whole heads; for a fixed row, one head's
// 64 cols live in ONE warp (8 nf x 2 cols x 4 thr) -> 8-FMA partial +
// shfl_xor over thr gives the complete per-head dot. Unique writers.
// ---------------------------------------------------------------------------
#define PSTG 4
#define PJA 3072
#define PROJ_SMEM ((PSTG * 2 * PJA) * 4)   // 98,304 B

__global__ __launch_bounds__(256, 2) void proj_mma(
    const float* __restrict__ rsb, const float* __restrict__ seg_embed,
    const float* __restrict__ rwb, const float* __restrict__ rrb)
{
    extern __shared__ unsigned psm[];
    unsigned* Asm = psm;
    unsigned* Bsm = psm + PSTG * PJA;

    const int rowbase = blockIdx.y * 128;
    const int colbase = blockIdx.x * 128;

    int abase, wsel, segbase;
    unsigned* Cu;
    float csc;
    if (rowbase < 2048)        { wsel = 0; segbase = 0;     abase = 2048; Cu = g_qb_u;  csc = 1.f;   }
    else if (rowbase < 6144)   { wsel = 1; segbase = 2048;  abase = 0;    Cu = g_kb_u;  csc = SCALE; }
    else if (rowbase < 10240)  { wsel = 2; segbase = 6144;  abase = 0;    Cu = g_vb_u;  csc = 1.f;   }
    else                       { wsel = 3; segbase = 10240; abase = 4096; Cu = g_krb_u; csc = SCALE; }
    const int crb = rowbase - segbase;

    const int tid = threadIdx.x;
    const int lane = tid & 31, warp = tid >> 5;
    const int wm = warp & 3, wn = warp >> 2;
    const int grp = lane >> 2, thr = lane & 3;
    const int rowA = (lane & 7) + (lane & 8);
    const int koA  = (lane & 16) >> 2;
    const int rowB = (lane & 7) + ((lane & 16) >> 1);
    const int kB   = (lane & 8) >> 1;

    const int arw = tid >> 1;
    const int asub = tid & 1;
    const unsigned* asrc = g_ab_u + (size_t)(abase + crb + arw) * 512 + asub * 8;
    const unsigned* bsrc = g_wpk_u + (size_t)wsel * 524288 + (size_t)(colbase + arw) * 512 + asub * 8;

    float acc[2][8][4];
#pragma unroll
    for (int mf = 0; mf < 2; mf++)
#pragma unroll
        for (int nf = 0; nf < 8; nf++)
#pragma unroll
            for (int q = 0; q < 4; q++) acc[mf][nf][q] = 0.f;

#define PROJ_ISSUE(it)                                                          \
    {                                                                           \
        int s_ = (it) & 3;                                                      \
        int k2base_ = (it) * 16;                                                \
        unsigned* ad = Asm + s_ * PJA + asub * 1536 + arw * 12;                 \
        cpa16(ad,     asrc + k2base_);                                          \
        cpa16(ad + 4, asrc + k2base_ + 4);                                      \
        unsigned* bd = Bsm + s_ * PJA + asub * 1536 + arw * 12;                 \
        cpa16(bd,     bsrc + k2base_);                                          \
        cpa16(bd + 4, bsrc + k2base_ + 4);                                      \
        CP_COMMIT();                                                            \
    }

    PROJ_ISSUE(0);
    PROJ_ISSUE(1);
    PROJ_ISSUE(2);

    for (int it = 0; it < 32; it++) {
        if (it >= 30) { CP_WAIT0(); } else { CP_WAIT2(); }
        __syncthreads();
        if (it + 3 < 32) PROJ_ISSUE(it + 3);
        const unsigned* Ast = Asm + (it & 3) * PJA;
        const unsigned* Bst = Bsm + (it & 3) * PJA;
#pragma unroll
        for (int s = 0; s < 2; s++) {
            const unsigned* As_ = Ast + s * 1536;
            const unsigned* Bs_ = Bst + s * 1536;
            unsigned a[2][4], bb[8][2];
#pragma unroll
            for (int mf = 0; mf < 2; mf++)
                ldsm_x4(a[mf][0], a[mf][1], a[mf][2], a[mf][3],
                        As_ + (wm * 32 + mf * 16 + rowA) * 12 + koA);
#pragma unroll
            for (int nf0 = 0; nf0 < 8; nf0 += 2) {
                unsigned t0, t1, t2, t3;
                ldsm_x4(t0, t1, t2, t3, Bs_ + (wn * 64 + nf0 * 8 + rowB) * 12 + kB);
                bb[nf0][0] = t0; bb[nf0][1] = t1;
                bb[nf0 + 1][0] = t2; bb[nf0 + 1][1] = t3;
            }
#pragma unroll
            for (int mf = 0; mf < 2; mf++)
#pragma unroll
                for (int nf = 0; nf < 8; nf++)
                    mma_bf16(acc[mf][nf], a[mf], bb[nf][0], bb[nf][1]);
        }
    }

    // ---- store bf16 outputs ----
#pragma unroll
    for (int mf = 0; mf < 2; mf++)
#pragma unroll
        for (int nf = 0; nf < 8; nf++) {
            int rr = crb + wm * 32 + mf * 16 + grp;
            int c2 = (colbase >> 1) + wn * 32 + nf * 4 + thr;
            Cu[(size_t)rr * 512 + c2] = pk2(acc[mf][nf][0] * csc, acc[mf][nf][1] * csc);
            Cu[(size_t)(rr + 8) * 512 + c2] = pk2(acc[mf][nf][2] * csc, acc[mf][nf][3] * csc);
        }

    // ---- fused bias reductions (post_kernel replacement) ----
    if (wsel != 2) {
        const int head = (colbase >> 6) + wn;   // global head index 0..15
        float pr0 = 0.f, pr1 = 0.f, pr2 = 0.f, pr3 = 0.f, rc = 0.f;
        if (wsel == 0) {
#pragma unroll
            for (int nf = 0; nf < 8; nf++) {
                int col = colbase + wn * 64 + nf * 8 + 2 * thr;
                float dx = seg_embed[1024 + col]     - seg_embed[col];
                float dy = seg_embed[1024 + col + 1] - seg_embed[col + 1];
                rc  += rsb[col] * dx + rsb[col + 1] * dy;
                pr0 += acc[0][nf][0] * dx + acc[0][nf][1] * dy;
                pr1 += acc[0][nf][2] * dx + acc[0][nf][3] * dy;
                pr2 += acc[1][nf][0] * dx + acc[1][nf][1] * dy;
                pr3 += acc[1][nf][2] * dx + acc[1][nf][3] * dy;
            }
#pragma unroll
            for (int o = 1; o < 4; o <<= 1) {
                rc  += __shfl_xor_sync(0xffffffffu, rc, o);
                pr0 += __shfl_xor_sync(0xffffffffu, pr0, o);
                pr1 += __shfl_xor_sync(0xffffffffu, pr1, o);
                pr2 += __shfl_xor_sync(0xffffffffu, pr2, o);
                pr3 += __shfl_xor_sync(0xffffffffu, pr3, o);
            }
            if (thr == 0) {
                int rb0 = crb + wm * 32 + grp;
                g_e[(size_t)rb0 * 16 + head]        = (pr0 + rc) * SCALE;
                g_e[(size_t)(rb0 + 8) * 16 + head]  = (pr1 + rc) * SCALE;
                g_e[(size_t)(rb0 + 16) * 16 + head] = (pr2 + rc) * SCALE;
                g_e[(size_t)(rb0 + 24) * 16 + head] = (pr3 + rc) * SCALE;
            }
        } else {
            const float* bias = (wsel == 1) ? rwb : rrb;
            float* dst = (wsel == 1) ? g_u : g_t;
#pragma unroll
            for (int nf = 0; nf < 8; nf++) {
                int col = colbase + wn * 64 + nf * 8 + 2 * thr;
                float2 bv = *(const float2*)(bias + col);
                pr0 += acc[0][nf][0] * bv.x + acc[0][nf][1] * bv.y;
                pr1 += acc[0][nf][2] * bv.x + acc[0][nf][3] * bv.y;
                pr2 += acc[1][nf][0] * bv.x + acc[1][nf][1] * bv.y;
                pr3 += acc[1][nf][2] * bv.x + acc[1][nf][3] * bv.y;
            }
#pragma unroll
            for (int o = 1; o < 4; o <<= 1) {
                pr0 += __shfl_xor_sync(0xffffffffu, pr0, o);
                pr1 += __shfl_xor_sync(0xffffffffu, pr1, o);
                pr2 += __shfl_xor_sync(0xffffffffu, pr2, o);
                pr3 += __shfl_xor_sync(0xffffffffu, pr3, o);
            }
            if (thr == 0) {
                int rb0 = crb + wm * 32 + grp;
                dst[(size_t)rb0 * 16 + head]        = pr0 * SCALE;
                dst[(size_t)(rb0 + 8) * 16 + head]  = pr1 * SCALE;
                dst[(size_t)(rb0 + 16) * 16 + head] = pr2 * SCALE;
                dst[(size_t)(rb0 + 24) * 16 + head] = pr3 * SCALE;
            }
        }
    }
#undef PROJ_ISSUE
}

// ---------------------------------------------------------------------------
// Output GEMM (bf16, 4-stage, ldmatrix frags): g_ao = g_avb @ wob^T.
// 64x128 tiles, grid (8,32)=256 blocks. 8 warps = 2m x 4n, warp tile 32x32.
// ---------------------------------------------------------------------------
#define OJS 4608
#define OUT_SMEM ((PSTG * OJS) * 4)    // 73,728 B

__global__ __launch_bounds__(256, 2) void out_mma()
{
    extern __shared__ unsigned psm[];

    const int rowbase = blockIdx.y * 64;
    const int colbase = blockIdx.x * 128;
    const int tid = threadIdx.x;
    const int lane = tid & 31, warp = tid >> 5;
    const int wm = warp & 1, wn = warp >> 1;
    const int grp = lane >> 2, thr = lane & 3;
    const int rowA = (lane & 7) + (lane & 8);
    const int koA  = (lane & 16) >> 2;
    const int rowB = (lane & 7) + ((lane & 16) >> 1);
    const int kB   = (lane & 8) >> 1;

    float acc[2][4][4];
#pragma unroll
    for (int mf = 0; mf < 2; mf++)
#pragma unroll
        for (int nf = 0; nf < 4; nf++)
#pragma unroll
            for (int q = 0; q < 4; q++) acc[mf][nf][q] = 0.f;

#define OUT_ISSUE(it)                                                           \
    {                                                                           \
        int s_ = (it) & 3;                                                      \
        int k2base_ = (it) * 16;                                                \
        {                                                                       \
            int row_ = tid >> 2;                                                \
            int sub_ = (tid & 2) >> 1;                                          \
            int half_ = tid & 1;                                                \
            cpa16(psm + s_ * OJS + sub_ * 768 + row_ * 12 + half_ * 4,          \
                  g_avb_u + (size_t)(rowbase + row_) * 512 + k2base_ +          \
                  sub_ * 8 + half_ * 4);                                        \
        }                                                                       \
        for (int t_ = tid; t_ < 512; t_ += 256) {                               \
            int row_ = t_ >> 2;                                                 \
            int sub_ = (t_ & 2) >> 1;                                           \
            int half_ = t_ & 1;                                                 \
            cpa16(psm + s_ * OJS + 1536 + sub_ * 1536 + row_ * 12 + half_ * 4,  \
                  g_wob_u + (size_t)(colbase + row_) * 512 + k2base_ +          \
                  sub_ * 8 + half_ * 4);                                        \
        }                                                                       \
        CP_COMMIT();                                                            \
    }

    OUT_ISSUE(0);
    OUT_ISSUE(1);
    OUT_ISSUE(2);

    for (int it = 0; it < 32; it++) {
        if (it >= 30) { CP_WAIT0(); } else { CP_WAIT2(); }
        __syncthreads();
        if (it + 3 < 32) OUT_ISSUE(it + 3);
        const unsigned* stg = psm + (it & 3) * OJS;
#pragma unroll
        for (int s = 0; s < 2; s++) {
            const unsigned* As_ = stg + s * 768;
            const unsigned* Bs_ = stg + 1536 + s * 1536;
            unsigned a[2][4], bb[4][2];
#pragma unroll
            for (int mf = 0; mf < 2; mf++)
                ldsm_x4(a[mf][0], a[mf][1], a[mf][2], a[mf][3],
                        As_ + (wm * 32 + mf * 16 + rowA) * 12 + koA);
#pragma unroll
            for (int nf0 = 0; nf0 < 4; nf0 += 2) {
                unsigned t0, t1, t2, t3;
                ldsm_x4(t0, t1, t2, t3, Bs_ + (wn * 32 + nf0 * 8 + rowB) * 12 + kB);
                bb[nf0][0] = t0; bb[nf0][1] = t1;
                bb[nf0 + 1][0] = t2; bb[nf0 + 1][1] = t3;
            }
#pragma unroll
            for (int mf = 0; mf < 2; mf++)
#pragma unroll
                for (int nf = 0; nf < 4; nf++)
                    mma_bf16(acc[mf][nf], a[mf], bb[nf][0], bb[nf][1]);
        }
    }
#pragma unroll
    for (int mf = 0; mf < 2; mf++)
#pragma unroll
        for (int nf = 0; nf < 4; nf++) {
            int rr = rowbase + wm * 32 + mf * 16 + grp;
            int cc = colbase + wn * 32 + nf * 8 + thr * 2;
            *(float2*)&g_ao[(size_t)rr * 1024 + cc] = make_float2(acc[mf][nf][0], acc[mf][nf][1]);
            *(float2*)&g_ao[(size_t)(rr + 8) * 1024 + cc] = make_float2(acc[mf][nf][2], acc[mf][nf][3]);
        }
#undef OUT_ISSUE
}

// ---------------------------------------------------------------------------
// Fused attention (R13 design): warp-local, ldmatrix frags, software-pipelined
// j-loop, 4-panel kr ring, P aliased onto Gw.
// smem 110,848 B -> 2 blocks/SM.
// ---------------------------------------------------------------------------
#define ATT_SMEM_BYTES (27712 * 4)

__global__ __launch_bounds__(256, 2) void attn_kernel()
{
    extern __shared__ unsigned smu[];
    unsigned* ksu2 = smu;                       // 2 x [64 x 36]
    unsigned* kru  = smu + 4608;                // 256 x 36 (4-panel ring)
    unsigned* vsu  = smu + 13824;               // 64 x 36
    float* Gw  = (float*)(smu + 16128);         // 8 x [16 x 88]  (P aliases)
    float* ub  = (float*)(smu + 27392);         // 64
    float* tb2 = (float*)(smu + 27456);         // 256 (4-panel ring)
    const __nv_bfloat16* vsb = (const __nv_bfloat16*)vsu;  // row stride 72 bf16

    const int b = blockIdx.x >> 4, n = blockIdx.x & 15;
    const int i0 = blockIdx.y * 128;
    const int tid = threadIdx.x;
    const int wm = tid >> 5, lane = tid & 31;
    const int grp = lane >> 2, thr = lane & 3;
    const int r0 = wm * 16 + grp;               // local rows r0, r0+8

    float* Gwp = Gw + wm * (16 * 88);
    unsigned* Pwp = (unsigned*)Gwp;             // alias (rows stride 36 u32)

    const int row16 = (lane & 7) + ((lane & 16) >> 1);  // B-frag rows
    const int koB   = (lane & 8) >> 1;
    const int rowA  = (lane & 7) + (lane & 8);          // A-frag rows
    const int koA   = (lane & 16) >> 2;
    const int rowV  = lane & 15;
    const int colV8 = (lane & 16) >> 1;

    // ---- q fragments straight from global bf16 ----
    unsigned qa[4][4];
#pragma unroll
    for (int kc = 0; kc < 4; kc++) {
        size_t b0 = ((size_t)(i0 + r0) * 4 + b) * 512 + n * 32 + kc * 8;
        size_t b1 = ((size_t)(i0 + r0 + 8) * 4 + b) * 512 + n * 32 + kc * 8;
        qa[kc][0] = g_qb_u[b0 + thr];
        qa[kc][1] = g_qb_u[b1 + thr];
        qa[kc][2] = g_qb_u[b0 + thr + 4];
        qa[kc][3] = g_qb_u[b1 + thr + 4];
    }

    float de0 = g_e[((size_t)(i0 + r0) * 4 + b) * 16 + n];
    float de1 = g_e[((size_t)(i0 + r0 + 8) * 4 + b) * 16 + n];

    float oacc[8][4];
#pragma unroll
    for (int nt = 0; nt < 8; nt++)
#pragma unroll
        for (int q = 0; q < 4; q++) oacc[nt][q] = 0.f;
    float rmax[2] = {-3.0e38f, -3.0e38f};
    float rsum[2] = {0.f, 0.f};

    const unsigned char* codeRow0 = g_code + ((size_t)b << 19) + (size_t)(i0 + r0) * 1024;
    const unsigned char* codeRow1 = codeRow0 + 8 * 1024;

    // ---- prologue: K0 + kr window0 (3 panels) ----
    const int base0 = 384 - i0;
    for (int t = tid; t < 512; t += 256) {
        int row = t >> 3, c = (t & 7) * 4;
        cpa16(&ksu2[row * 36 + c],
              g_kb_u + ((size_t)row * 4 + b) * 512 + n * 32 + c);
    }
    for (int t = tid; t < 192 * 8; t += 256) {
        int o = t >> 3, c = (t & 7) * 4;
        cpa16(&kru[SLAB4(base0 + o) * 36 + c],
              g_krb_u + ((size_t)(base0 + o) * 4 + b) * 512 + n * 32 + c);
    }
    CP_COMMIT();
    if (tid < 192)
        tb2[SLAB4(base0 + tid)] = g_t[((size_t)(base0 + tid) * 4 + b) * 16 + n];

    for (int j0 = 0; j0 < KLEN; j0 += 64) {
        const int ji = j0 >> 6;
        const int base = j0 - i0 + 384;
        __syncthreads();                         // prior-iter reads done
        // ---- issue V(j) ----
        for (int t = tid; t < 512; t += 256) {
            int row = t >> 3, c = (t & 7) * 4;
            cpa16(&vsu[row * 36 + c],
                  g_vb_u + ((size_t)(j0 + row) * 4 + b) * 512 + n * 32 + c);
        }
        CP_COMMIT();
        // ---- issue K(j+1) + kr-panel(j+1) (prefetch one iter ahead) ----
        if (j0 + 64 < KLEN) {
            unsigned* ksn = ksu2 + ((ji + 1) & 1) * 2304;
            for (int t = tid; t < 512; t += 256) {
                int row = t >> 3, c = (t & 7) * 4;
                cpa16(&ksn[row * 36 + c],
                      g_kb_u + ((size_t)(j0 + 64 + row) * 4 + b) * 512 + n * 32 + c);
            }
            for (int t = tid; t < 512; t += 256) {
                int o = 192 + (t >> 3), c = (t & 7) * 4;
                cpa16(&kru[SLAB4(base + o) * 36 + c],
                      g_krb_u + ((size_t)(base + o) * 4 + b) * 512 + n * 32 + c);
            }
        }
        CP_COMMIT();
        // ---- scalar ub(j) + tb panel(j+1) ----
        if (tid < 64) {
            ub[tid] = g_u[((size_t)(j0 + tid) * 4 + b) * 16 + n];
        } else if (tid < 128 && j0 + 64 < KLEN) {
            int o = 192 + (tid - 64);
            tb2[SLAB4(base + o)] = g_t[((size_t)(base + o) * 4 + b) * 16 + n];
        }
        CP_WAIT2();          // completes group with K(j)/kr(j) (issued iter j-1)
        __syncthreads();

        // ---- S = q @ k^T ----
        const unsigned* ksc = ksu2 + (ji & 1) * 2304;
        float sacc[8][4];
#pragma unroll
        for (int nt = 0; nt < 8; nt++)
#pragma unroll
            for (int q = 0; q < 4; q++) sacc[nt][q] = 0.f;
#pragma unroll
        for (int kc = 0; kc < 4; kc++) {
#pragma unroll
            for (int p = 0; p < 4; p++) {
                unsigned k0, k1, k2, k3;
                ldsm_x4(k0, k1, k2, k3, &ksc[(16 * p + row16) * 36 + kc * 8 + koB]);
                mma_bf16(sacc[2 * p], qa[kc], k0, k1);
                mma_bf16(sacc[2 * p + 1], qa[kc], k2, k3);
            }
        }

        // ---- per-warp band G (16 x 80), +t folded at store (float2) ----
        const int woff = 112 - wm * 16;
#pragma unroll
        for (int p = 0; p < 5; p++) {
            int o = woff + 16 * p + row16;
            int srow = SLAB4(base + o);
            float ga[4] = {0.f, 0.f, 0.f, 0.f};
            float gb[4] = {0.f, 0.f, 0.f, 0.f};
#pragma unroll
            for (int kc = 0; kc < 4; kc++) {
                unsigned k0, k1, k2, k3;
                ldsm_x4(k0, k1, k2, k3, &kru[srow * 36 + kc * 8 + koB]);
                mma_bf16(ga, qa[kc], k0, k1);
                mma_bf16(gb, qa[kc], k2, k3);
            }
            int g0 = 16 * p + 2 * thr;
            int oA = woff + g0;
            float2 tA = *(float2*)&tb2[SLAB4(base + oA)];
            int oB = oA + 8;
            float2 tB = *(float2*)&tb2[SLAB4(base + oB)];
            *(float2*)&Gwp[grp * 88 + g0]           = make_float2(ga[0] + tA.x, ga[1] + tA.y);
            *(float2*)&Gwp[(grp + 8) * 88 + g0]     = make_float2(ga[2] + tA.x, ga[3] + tA.y);
            *(float2*)&Gwp[grp * 88 + g0 + 8]       = make_float2(gb[0] + tB.x, gb[1] + tB.y);
            *(float2*)&Gwp[(grp + 8) * 88 + g0 + 8] = make_float2(gb[2] + tB.x, gb[3] + tB.y);
        }
        __syncwarp();

        // ---- assemble logits, warp-local row maxes ----
        float mx0 = -3.0e38f, mx1 = -3.0e38f;
#pragma unroll
        for (int nt = 0; nt < 8; nt++) {
            int c = nt * 8 + 2 * thr;
            int gi  = c - grp + 16;
            int gi2 = c - grp + 8;
            float G00, G01, G10, G11;
            if ((grp & 1) == 0) {
                float2 fa = *(float2*)&Gwp[grp * 88 + gi];
                float2 fb = *(float2*)&Gwp[(grp + 8) * 88 + gi2];
                G00 = fa.x; G01 = fa.y; G10 = fb.x; G11 = fb.y;
            } else {
                G00 = Gwp[grp * 88 + gi];
                G01 = Gwp[grp * 88 + gi + 1];
                G10 = Gwp[(grp + 8) * 88 + gi2];
                G11 = Gwp[(grp + 8) * 88 + gi2 + 1];
            }
            unsigned short w0 = *(const unsigned short*)(codeRow0 + j0 + c);
            unsigned short w1 = *(const unsigned short*)(codeRow1 + j0 + c);
            float2 uu = *(float2*)&ub[c];
            float v;
            v = sacc[nt][0] + G00 + uu.x + ((w0 & 1) ? de0 : 0.f);
            if (w0 & 2) v -= 1e30f;
            sacc[nt][0] = v; mx0 = fmaxf(mx0, v);
            v = sacc[nt][1] + G01 + uu.y + ((w0 & 256) ? de0 : 0.f);
            if (w0 & 512) v -= 1e30f;
            sacc[nt][1] = v; mx0 = fmaxf(mx0, v);
            v = sacc[nt][2] + G10 + uu.x + ((w1 & 1) ? de1 : 0.f);
            if (w1 & 2) v -= 1e30f;
            sacc[nt][2] = v; mx1 = fmaxf(mx1, v);
            v = sacc[nt][3] + G11 + uu.y + ((w1 & 256) ? de1 : 0.f);
            if (w1 & 512) v -= 1e30f;
            sacc[nt][3] = v; mx1 = fmaxf(mx1, v);
        }
        // shuffle reductions also order G reads before P writes (alias)
#pragma unroll
        for (int o = 1; o < 4; o <<= 1) {
            mx0 = fmaxf(mx0, __shfl_xor_sync(0xffffffffu, mx0, o));
            mx1 = fmaxf(mx1, __shfl_xor_sync(0xffffffffu, mx1, o));
        }
        float nm0 = fmaxf(rmax[0], mx0);
        float nm1 = fmaxf(rmax[1], mx1);
        float corr0 = __expf(rmax[0] - nm0);
        float corr1 = __expf(rmax[1] - nm1);
        rmax[0] = nm0; rmax[1] = nm1;

        float sum0 = 0.f, sum1 = 0.f;
#pragma unroll
        for (int nt = 0; nt < 8; nt++) {
            float p0 = __expf(sacc[nt][0] - nm0);
            float p1 = __expf(sacc[nt][1] - nm0);
            float p2 = __expf(sacc[nt][2] - nm1);
            float p3 = __expf(sacc[nt][3] - nm1);
            sum0 += p0 + p1; sum1 += p2 + p3;
            Pwp[grp * 36 + nt * 4 + thr] = pk2(p0, p1);
            Pwp[(grp + 8) * 36 + nt * 4 + thr] = pk2(p2, p3);
        }
#pragma unroll
        for (int o = 1; o < 4; o <<= 1) {
            sum0 += __shfl_xor_sync(0xffffffffu, sum0, o);
            sum1 += __shfl_xor_sync(0xffffffffu, sum1, o);
        }
        rsum[0] = rsum[0] * corr0 + sum0;
        rsum[1] = rsum[1] * corr1 + sum1;

        CP_WAIT1();          // V(j) ready (prefetch group for j+1 may remain)
        __syncthreads();

        // ---- O = O*corr + P @ V ----
#pragma unroll
        for (int nt = 0; nt < 8; nt++) {
            oacc[nt][0] *= corr0; oacc[nt][1] *= corr0;
            oacc[nt][2] *= corr1; oacc[nt][3] *= corr1;
        }
#pragma unroll
        for (int kc = 0; kc < 4; kc++) {
            unsigned a[4];
            ldsm_x4(a[0], a[1], a[2], a[3], &Pwp[rowA * 36 + kc * 8 + koA]);
#pragma unroll
            for (int p = 0; p < 4; p++) {
                unsigned v0, v1, v2, v3;
                ldsm_x4_t(v0, v1, v2, v3,
                          vsb + (kc * 16 + rowV) * 72 + p * 16 + colV8);
                mma_bf16(oacc[2 * p], a, v0, v1);
                mma_bf16(oacc[2 * p + 1], a, v2, v3);
            }
        }
    }

    // ---- write normalized output (bf16) ----
    float inv0 = 1.f / rsum[0];
    float inv1 = 1.f / rsum[1];
#pragma unroll
    for (int nt = 0; nt < 8; nt++) {
        int d2 = n * 32 + nt * 4 + thr;
        g_avb_u[((size_t)(i0 + r0) * 4 + b) * 512 + d2] =
            pk2(oacc[nt][0] * inv0, oacc[nt][1] * inv0);
        g_avb_u[((size_t)(i0 + r0 + 8) * 4 + b) * 512 + d2] =
            pk2(oacc[nt][2] * inv1, oacc[nt][3] * inv1);
    }
}

// ---------------------------------------------------------------------------
// Residual + LayerNorm (single pass, float4)
// ---------------------------------------------------------------------------
__global__ __launch_bounds__(256) void ln_kernel(
    const float* __restrict__ hres, const float* __restrict__ gamma,
    const float* __restrict__ beta, float* __restrict__ out)
{
    __shared__ float4 xb4[256];
    __shared__ float red1[8], red2[8];
    const int row = blockIdx.x;
    const int tid = threadIdx.x;

    float4 a4 = *(const float4*)(g_ao + (size_t)row * 1024 + tid * 4);
    float4 h4 = *(const float4*)(hres + (size_t)row * 1024 + tid * 4);
    float4 x4 = make_float4(a4.x + h4.x, a4.y + h4.y, a4.z + h4.z, a4.w + h4.w);
    xb4[tid] = x4;
    float s = x4.x + x4.y + x4.z + x4.w;
    float s2 = x4.x * x4.x + x4.y * x4.y + x4.z * x4.z + x4.w * x4.w;
#pragma unroll
    for (int o = 16; o; o >>= 1) {
        s += __shfl_xor_sync(0xffffffffu, s, o);
        s2 += __shfl_xor_sync(0xffffffffu, s2, o);
    }
    if ((tid & 31) == 0) { red1[tid >> 5] = s; red2[tid >> 5] = s2; }
    __syncthreads();
    float tot = 0.f, tot2 = 0.f;
#pragma unroll
    for (int k = 0; k < 8; k++) { tot += red1[k]; tot2 += red2[k]; }
    const float mean = tot * (1.f / 1024.f);
    const float var = tot2 * (1.f / 1024.f) - mean * mean;
    const float inv = rsqrtf(var + LN_EPS);

    float4 g4 = *(const float4*)(gamma + tid * 4);
    float4 b4 = *(const float4*)(beta + tid * 4);
    float4 xx = xb4[tid];
    float4 o4;
    o4.x = (xx.x - mean) * inv * g4.x + b4.x;
    o4.y = (xx.y - mean) * inv * g4.y + b4.y;
    o4.z = (xx.z - mean) * inv * g4.z + b4.z;
    o4.w = (xx.w - mean) * inv * g4.w + b4.w;
    *(float4*)(out + (size_t)row * 1024 + tid * 4) = o4;
}

// ---------------------------------------------------------------------------
extern "C" void kernel_launch(void* const* d_in, const int* in_sizes, int n_in,
                              void* d_out, int out_size)
{
    const float* rwb       = (const float*)d_in[0];
    const float* rsb       = (const float*)d_in[1];
    const float* rrb       = (const float*)d_in[2];
    const float* seg_embed = (const float*)d_in[3];
    const float* h         = (const float*)d_in[4];
    const float* r         = (const float*)d_in[5];
    const float* mems      = (const float*)d_in[6];
    const float* seg_mat   = (const float*)d_in[7];
    const float* attn_mask = (const float*)d_in[8];
    const float* wq        = (const float*)d_in[9];
    const float* wk        = (const float*)d_in[10];
    const float* wv        = (const float*)d_in[11];
    const float* wr        = (const float*)d_in[12];
    const float* wo        = (const float*)d_in[13];
    const float* gamma     = (const float*)d_in[14];
    const float* beta      = (const float*)d_in[15];

    cudaFuncSetAttribute(attn_kernel, cudaFuncAttributeMaxDynamicSharedMemorySize, ATT_SMEM_BYTES);
    cudaFuncSetAttribute(proj_mma, cudaFuncAttributeMaxDynamicSharedMemorySize, PROJ_SMEM);
    cudaFuncSetAttribute(out_mma, cudaFuncAttributeMaxDynamicSharedMemorySize, OUT_SMEM);

    prep_kernel<<<21504, 256>>>(mems, h, r, wo, seg_mat, attn_mask, wq, wk, wv, wr);
    proj_mma<<<dim3(8, 128), 256, PROJ_SMEM>>>(rsb, seg_embed, rwb, rrb);
    attn_kernel<<<dim3(64, 4), 256, ATT_SMEM_BYTES>>>();
    out_mma<<<dim3(8, 32), 256, OUT_SMEM>>>();
    ln_kernel<<<2048, 256>>>(h, gamma, beta, (float*)d_out);
}